// round 11
// baseline (speedup 1.0000x reference)
#include <cuda_runtime.h>

#define N_NODES 50000
#define N_EDGES 200000
#define C 32
#define ND 75
#define ED 12
#define NL 3
#define NG 500
#define HID 5
#define BN_EPS 1e-5f

// Scratch (no allocations allowed)
__device__ __align__(128) float g_h[N_NODES * C];         // layer-0 features (row-major)
__device__ __align__(128) float g_hn[N_NODES * C];        // normalized h for layers 1,2
__device__ __align__(128) float g_agg[N_NODES * C];       // conv accumulator
__device__ __align__(128) float g_v[N_NODES * 6 * C];     // v[n,k,d]
__device__ __align__(128) float g_coef[NL * N_EDGES * 8]; // edge MLP coefs, padded
__device__ float g_stats[2 * C];                          // BN sum / sumsq

// ---- packed fp32x2 helpers (sm_103a) ----
__device__ __forceinline__ void fma2(unsigned long long& acc, unsigned long long a,
                                     unsigned long long b) {
    asm("fma.rn.f32x2 %0, %1, %2, %0;" : "+l"(acc) : "l"(a), "l"(b));
}
__device__ __forceinline__ unsigned long long pack2(float v) {
    unsigned long long r;
    asm("mov.b64 %0, {%1, %1};" : "=l"(r) : "f"(v));
    return r;
}
__device__ __forceinline__ void red_add_v4(float* addr, float4 v) {
    asm volatile("red.global.add.v4.f32 [%0], {%1, %2, %3, %4};"
                 :: "l"(addr), "f"(v.x), "f"(v.y), "f"(v.z), "f"(v.w) : "memory");
}

// ---------------------------------------------------------------------------
// h = leaky(x @ lin_W + lin_b)   (R6 row-major version, known-good)
// ---------------------------------------------------------------------------
__global__ void __launch_bounds__(256) k_init(const float* __restrict__ x,
                                              const float* __restrict__ W,
                                              const float* __restrict__ b) {
    __shared__ __align__(16) float sW[ND * C];
    __shared__ float sb[C];
    for (int i = threadIdx.x; i < ND * C; i += blockDim.x) sW[i] = W[i];
    if (threadIdx.x < C) sb[threadIdx.x] = b[threadIdx.x];
    __syncthreads();
    int n = blockIdx.x * blockDim.x + threadIdx.x;
    if (n >= N_NODES) return;
    float acc[C];
#pragma unroll
    for (int d = 0; d < C; d++) acc[d] = sb[d];
    const float* xr = x + (size_t)n * ND;
#pragma unroll 5
    for (int j = 0; j < ND; j++) {
        float xv = __ldg(xr + j);
#pragma unroll
        for (int d = 0; d < C; d++) acc[d] += xv * sW[j * C + d];
    }
    float4* ho = (float4*)(g_h + (size_t)n * C);
#pragma unroll
    for (int q = 0; q < 8; q++) {
        float4 v;
        float a0 = acc[4 * q], a1 = acc[4 * q + 1], a2 = acc[4 * q + 2], a3 = acc[4 * q + 3];
        v.x = a0 > 0.f ? a0 : 0.01f * a0;
        v.y = a1 > 0.f ? a1 : 0.01f * a1;
        v.z = a2 > 0.f ? a2 : 0.01f * a2;
        v.w = a3 > 0.f ? a3 : 0.01f * a3;
        ho[q] = v;
    }
}

// ---------------------------------------------------------------------------
// Precompute edge-MLP coefs for ALL layers (edge_attr is layer-invariant).
// ---------------------------------------------------------------------------
__global__ void __launch_bounds__(256) k_coef(const float* __restrict__ ea,
                                              const float* __restrict__ W1,
                                              const float* __restrict__ b1) {
    __shared__ float sW1[NL * ED * HID];
    __shared__ float sb1[NL * HID];
    if (threadIdx.x < NL * ED * HID) sW1[threadIdx.x] = W1[threadIdx.x];
    if (threadIdx.x < NL * HID) sb1[threadIdx.x] = b1[threadIdx.x];
    __syncthreads();
    int e = blockIdx.x * blockDim.x + threadIdx.x;
    if (e >= N_EDGES) return;
    float eav[ED];
    const float4* ear = (const float4*)(ea + (size_t)e * ED);
#pragma unroll
    for (int q = 0; q < 3; q++) {
        float4 v = ear[q];
        eav[4 * q] = v.x; eav[4 * q + 1] = v.y; eav[4 * q + 2] = v.z; eav[4 * q + 3] = v.w;
    }
#pragma unroll
    for (int l = 0; l < NL; l++) {
        float out[8];
#pragma unroll
        for (int k = 0; k < HID; k++) {
            float s = sb1[l * HID + k];
#pragma unroll
            for (int j = 0; j < ED; j++) s += eav[j] * sW1[(l * ED + j) * HID + k];
            out[k] = fmaxf(s, 0.f);
        }
        out[5] = 1.f; out[6] = 0.f; out[7] = 0.f;
        float4* co = (float4*)(g_coef + ((size_t)l * N_EDGES + e) * 8);
        co[0] = make_float4(out[0], out[1], out[2], out[3]);
        co[1] = make_float4(out[4], out[5], out[6], out[7]);
    }
}

// ---------------------------------------------------------------------------
// k_v, 8-lane geometry (THE single change this round):
// warp-item = (slot, 4 nodes); lane = (node g, output-slice d4).
//   slots 0..4: h @ W2[k] -> g_v ; 5: h @ b2 -> g_v ; 6: h @ rootW + cb -> agg
// Loads:  8 LDG.128/warp, 4 lines each (8-way broadcast within node).
// Weights: conflict-free broadcast LDS.128.
// Stores: 1 STG.128/warp touching 4 lines (optimal).
// Grid-stride (1184 blocks) so weights load once per block.
// Even/odd-c split accumulators halve the FMA RAW chain.
// ---------------------------------------------------------------------------
__global__ void __launch_bounds__(256) k_v(const float* __restrict__ W2,
                                           const float* __restrict__ b2,
                                           const float* __restrict__ rootW,
                                           const float* __restrict__ cbv,
                                           int layer) {
    __shared__ __align__(16) float sW[7 * C * C];   // 28 KB
    __shared__ float sCB[C];
    for (int i = threadIdx.x; i < HID * C * C; i += 256) sW[i] = W2[i];
    for (int i = threadIdx.x; i < C * C; i += 256) {
        sW[5 * C * C + i] = b2[i];
        sW[6 * C * C + i] = rootW[i];
    }
    if (threadIdx.x < C) sCB[threadIdx.x] = cbv[threadIdx.x];
    __syncthreads();

    const float* hin = (layer == 0) ? g_h : g_hn;
    int lane = threadIdx.x & 31;
    int g = lane >> 3;              // node within 4-node group
    int cb4 = (lane & 7) * 4;       // output column base
    int w0 = blockIdx.x * 8 + (threadIdx.x >> 5);
    const int TOT = 7 * (N_NODES / 4);   // 87500
    int wstride = gridDim.x * 8;

    for (int it = w0; it < TOT; it += wstride) {
        int slot = it % 7;
        int grp = it / 7;
        int node = grp * 4 + g;
        const float4* hr = (const float4*)(hin + (size_t)node * C);
        const float* wb = sW + slot * C * C + cb4;
        unsigned long long a0 = 0ULL, a1 = 0ULL;   // even channels
        unsigned long long c0 = 0ULL, c1 = 0ULL;   // odd channels
#pragma unroll
        for (int ch = 0; ch < 8; ch += 2) {
            float4 h0 = __ldg(hr + ch);
            float4 h1 = __ldg(hr + ch + 1);
            {
                unsigned long long p = pack2(h0.x);
                ulonglong2 ww = *(const ulonglong2*)(wb + (ch * 4 + 0) * C);
                fma2(a0, p, ww.x); fma2(a1, p, ww.y);
            }
            {
                unsigned long long p = pack2(h0.y);
                ulonglong2 ww = *(const ulonglong2*)(wb + (ch * 4 + 1) * C);
                fma2(c0, p, ww.x); fma2(c1, p, ww.y);
            }
            {
                unsigned long long p = pack2(h0.z);
                ulonglong2 ww = *(const ulonglong2*)(wb + (ch * 4 + 2) * C);
                fma2(a0, p, ww.x); fma2(a1, p, ww.y);
            }
            {
                unsigned long long p = pack2(h0.w);
                ulonglong2 ww = *(const ulonglong2*)(wb + (ch * 4 + 3) * C);
                fma2(c0, p, ww.x); fma2(c1, p, ww.y);
            }
            {
                unsigned long long p = pack2(h1.x);
                ulonglong2 ww = *(const ulonglong2*)(wb + (ch * 4 + 4) * C);
                fma2(a0, p, ww.x); fma2(a1, p, ww.y);
            }
            {
                unsigned long long p = pack2(h1.y);
                ulonglong2 ww = *(const ulonglong2*)(wb + (ch * 4 + 5) * C);
                fma2(c0, p, ww.x); fma2(c1, p, ww.y);
            }
            {
                unsigned long long p = pack2(h1.z);
                ulonglong2 ww = *(const ulonglong2*)(wb + (ch * 4 + 6) * C);
                fma2(a0, p, ww.x); fma2(a1, p, ww.y);
            }
            {
                unsigned long long p = pack2(h1.w);
                ulonglong2 ww = *(const ulonglong2*)(wb + (ch * 4 + 7) * C);
                fma2(c0, p, ww.x); fma2(c1, p, ww.y);
            }
        }
        float2 ae = *(float2*)&a0, be = *(float2*)&a1;
        float2 ao = *(float2*)&c0, bo = *(float2*)&c1;
        float r0 = ae.x + ao.x, r1 = ae.y + ao.y;
        float r2 = be.x + bo.x, r3 = be.y + bo.y;
        if (slot == 6) {
            *(float4*)(g_agg + (size_t)node * C + cb4) =
                make_float4(r0 + sCB[cb4], r1 + sCB[cb4 + 1],
                            r2 + sCB[cb4 + 2], r3 + sCB[cb4 + 3]);
        } else {
            *(float4*)(g_v + (size_t)node * 192 + slot * C + cb4) =
                make_float4(r0, r1, r2, r3);
        }
    }
}

// ---------------------------------------------------------------------------
// Edge kernel (unchanged, measured 17us): 8 lanes per edge (warp = 4 edges).
// Block 0 zeroes g_stats for this layer's k_stats.
// ---------------------------------------------------------------------------
__global__ void __launch_bounds__(256) k_edge(const int* __restrict__ src,
                                              const int* __restrict__ dst,
                                              int layer) {
    if (blockIdx.x == 0 && threadIdx.x < 2 * C) g_stats[threadIdx.x] = 0.f;

    const float* coefL = g_coef + (size_t)layer * N_EDGES * 8;

    int lane = threadIdx.x & 31;
    int warp = (blockIdx.x * blockDim.x + threadIdx.x) >> 5;
    int group = lane >> 3;
    int d4 = lane & 7;
    int e = warp * 4 + group;
    if (e >= N_EDGES) return;

    int sn = __ldg(src + e);
    int dn = __ldg(dst + e);
    const float* cp = coefL + (size_t)e * 8;
    float4 c03 = __ldg((const float4*)cp);
    float2 c45 = __ldg((const float2*)(cp + 4));
    float coef[6] = {c03.x, c03.y, c03.z, c03.w, c45.x, c45.y};

    unsigned long long a0 = 0ULL, a1 = 0ULL;
    const float* vb = g_v + (size_t)sn * (6 * C) + d4 * 4;
#pragma unroll
    for (int k = 0; k < 6; k++) {
        float ck = coef[k];
        if (ck != 0.f) {
            ulonglong2 w = __ldg((const ulonglong2*)(vb + k * C));
            unsigned long long p = pack2(ck);
            fma2(a0, p, w.x);
            fma2(a1, p, w.y);
        }
    }

    float2 lo = *(float2*)&a0, hi = *(float2*)&a1;
    red_add_v4(g_agg + (size_t)dn * C + d4 * 4, make_float4(lo.x, lo.y, hi.x, hi.y));
}

// ---------------------------------------------------------------------------
// BN statistics over g_agg; for the last layer, blocks 0-1 seed out with pred_b.
// ---------------------------------------------------------------------------
__global__ void __launch_bounds__(256) k_stats(float* out, const float* __restrict__ pb,
                                               int do_out) {
    if (do_out && blockIdx.x < 2) {
        int g = blockIdx.x * 256 + threadIdx.x;
        if (g < NG) out[g] = pb[0];
    }
    __shared__ float ss[2 * C];
    if (threadIdx.x < 2 * C) ss[threadIdx.x] = 0.f;
    __syncthreads();
    const float4* A = (const float4*)g_agg;
    float4 s = {0.f, 0.f, 0.f, 0.f}, q = {0.f, 0.f, 0.f, 0.f};
    int stride = gridDim.x * blockDim.x;
    for (int i = blockIdx.x * blockDim.x + threadIdx.x; i < N_NODES * 8; i += stride) {
        float4 v = A[i];
        s.x += v.x; s.y += v.y; s.z += v.z; s.w += v.w;
        q.x += v.x * v.x; q.y += v.y * v.y; q.z += v.z * v.z; q.w += v.w * v.w;
    }
#pragma unroll
    for (int off = 8; off <= 16; off <<= 1) {
        s.x += __shfl_xor_sync(0xffffffffu, s.x, off);
        s.y += __shfl_xor_sync(0xffffffffu, s.y, off);
        s.z += __shfl_xor_sync(0xffffffffu, s.z, off);
        s.w += __shfl_xor_sync(0xffffffffu, s.w, off);
        q.x += __shfl_xor_sync(0xffffffffu, q.x, off);
        q.y += __shfl_xor_sync(0xffffffffu, q.y, off);
        q.z += __shfl_xor_sync(0xffffffffu, q.z, off);
        q.w += __shfl_xor_sync(0xffffffffu, q.w, off);
    }
    int lane = threadIdx.x & 31;
    if (lane < 8) {
        int cg = lane * 4;
        atomicAdd(&ss[cg + 0], s.x); atomicAdd(&ss[cg + 1], s.y);
        atomicAdd(&ss[cg + 2], s.z); atomicAdd(&ss[cg + 3], s.w);
        atomicAdd(&ss[C + cg + 0], q.x); atomicAdd(&ss[C + cg + 1], q.y);
        atomicAdd(&ss[C + cg + 2], q.z); atomicAdd(&ss[C + cg + 3], q.w);
    }
    __syncthreads();
    if (threadIdx.x < 2 * C) atomicAdd(&g_stats[threadIdx.x], ss[threadIdx.x]);
}

// ---------------------------------------------------------------------------
// k_norm: g_hn = leaky(BN(g_agg)), row-major elementwise (both sides coalesced).
// ---------------------------------------------------------------------------
__global__ void __launch_bounds__(256) k_norm(const float* __restrict__ bng,
                                              const float* __restrict__ bnb) {
    __shared__ float sA[C], sB[C];
    if (threadIdx.x < C) {
        float mu = g_stats[threadIdx.x] * (1.0f / N_NODES);
        float var = g_stats[C + threadIdx.x] * (1.0f / N_NODES) - mu * mu;
        float Av = rsqrtf(var + BN_EPS) * bng[threadIdx.x];
        sA[threadIdx.x] = Av;
        sB[threadIdx.x] = bnb[threadIdx.x] - mu * Av;
    }
    __syncthreads();
    const float4* A = (const float4*)g_agg;
    float4* O = (float4*)g_hn;
    int stride = gridDim.x * blockDim.x;
    for (int i = blockIdx.x * blockDim.x + threadIdx.x; i < N_NODES * 8; i += stride) {
        int c0 = (i & 7) * 4;
        float4 v = A[i];
        v.x = v.x * sA[c0] + sB[c0];         v.x = v.x > 0.f ? v.x : 0.01f * v.x;
        v.y = v.y * sA[c0 + 1] + sB[c0 + 1]; v.y = v.y > 0.f ? v.y : 0.01f * v.y;
        v.z = v.z * sA[c0 + 2] + sB[c0 + 2]; v.z = v.z > 0.f ? v.z : 0.01f * v.z;
        v.w = v.w * sA[c0 + 3] + sB[c0 + 3]; v.w = v.w > 0.f ? v.w : 0.01f * v.w;
        O[i] = v;
    }
}

// ---------------------------------------------------------------------------
// Final: BN (no leaky) + prediction dot + scatter to graphs (batch is sorted).
// Tail lanes clamp and contribute 0 (all collectives full-warp).
// ---------------------------------------------------------------------------
__global__ void __launch_bounds__(256) k_fin(const int* __restrict__ batch,
                                             const float* __restrict__ pW,
                                             const float* __restrict__ bng,
                                             const float* __restrict__ bnb,
                                             float* out) {
    __shared__ float snorm[4 * C];
    __shared__ float spw[C];
    if (threadIdx.x < C) {
        float mu = g_stats[threadIdx.x] * (1.0f / N_NODES);
        float var = g_stats[C + threadIdx.x] * (1.0f / N_NODES) - mu * mu;
        snorm[threadIdx.x] = mu;
        snorm[C + threadIdx.x] = rsqrtf(var + BN_EPS);
        snorm[2 * C + threadIdx.x] = bng[threadIdx.x];
        snorm[3 * C + threadIdx.x] = bnb[threadIdx.x];
        spw[threadIdx.x] = pW[threadIdx.x];
    }
    __syncthreads();
    int n = blockIdx.x * blockDim.x + threadIdx.x;
    bool valid = n < N_NODES;
    int nn = valid ? n : N_NODES - 1;
    const float4* ap = (const float4*)(g_agg + (size_t)nn * C);
    float s = 0.f;
#pragma unroll
    for (int q = 0; q < 8; q++) {
        float4 v = ap[q];
        float t[4] = {v.x, v.y, v.z, v.w};
#pragma unroll
        for (int r = 0; r < 4; r++) {
            int c = 4 * q + r;
            float val = (t[r] - snorm[c]) * snorm[C + c] * snorm[2 * C + c] + snorm[3 * C + c];
            s += val * spw[c];
        }
    }
    if (!valid) s = 0.f;
    int bid = batch[nn];
    int bid0 = __shfl_sync(0xffffffffu, bid, 0);
    bool uni = __all_sync(0xffffffffu, bid == bid0 && valid);
    if (uni) {
#pragma unroll
        for (int off = 16; off >= 1; off >>= 1)
            s += __shfl_xor_sync(0xffffffffu, s, off);
        if ((threadIdx.x & 31) == 0) atomicAdd(&out[bid0], s);
    } else if (valid) {
        atomicAdd(&out[bid], s);
    }
}

// ---------------------------------------------------------------------------
extern "C" void kernel_launch(void* const* d_in, const int* in_sizes, int n_in,
                              void* d_out, int out_size) {
    const float* x       = (const float*)d_in[0];
    const int*   ei      = (const int*)d_in[1];
    const float* ea      = (const float*)d_in[2];
    const int*   batch   = (const int*)d_in[3];
    const float* lin_W   = (const float*)d_in[4];
    const float* lin_b   = (const float*)d_in[5];
    const float* mes_W1  = (const float*)d_in[6];
    const float* mes_b1  = (const float*)d_in[7];
    const float* mes_W2  = (const float*)d_in[8];
    const float* mes_b2  = (const float*)d_in[9];
    const float* root_W  = (const float*)d_in[10];
    const float* conv_b  = (const float*)d_in[11];
    const float* bn_g    = (const float*)d_in[12];
    const float* bn_b    = (const float*)d_in[13];
    const float* pred_W  = (const float*)d_in[14];
    const float* pred_b  = (const float*)d_in[15];
    float* out = (float*)d_out;

    const int* src = ei;
    const int* dst = ei + N_EDGES;

    int eblocks = (N_EDGES / 4 * 32 + 255) / 256;    // 6250

    k_init<<<(N_NODES + 255) / 256, 256>>>(x, lin_W, lin_b);
    k_coef<<<(N_EDGES + 255) / 256, 256>>>(ea, mes_W1, mes_b1);
    for (int l = 0; l < NL; l++) {
        k_v<<<1184, 256>>>(mes_W2 + l * HID * C * C, mes_b2 + l * C * C,
                           root_W + l * C * C, conv_b + l * C, l);
        k_edge<<<eblocks, 256>>>(src, dst, l);
        k_stats<<<1184, 256>>>(out, pred_b, l == NL - 1 ? 1 : 0);
        if (l < NL - 1) k_norm<<<592, 256>>>(bn_g + l * C, bn_b + l * C);
    }
    k_fin<<<(N_NODES + 255) / 256, 256>>>(batch, pred_W, bn_g + 2 * C, bn_b + 2 * C, out);
}

// round 12
// speedup vs baseline: 1.1053x; 1.1053x over previous
#include <cuda_runtime.h>

#define N_NODES 50000
#define N_EDGES 200000
#define C 32
#define ND 75
#define ED 12
#define NL 3
#define NG 500
#define HID 5
#define BN_EPS 1e-5f

// Scratch (no allocations allowed)
__device__ __align__(128) float g_h[N_NODES * C];         // layer-0 features
__device__ __align__(128) float g_agg[N_NODES * C];       // conv accumulator / h carrier
__device__ __align__(128) float g_v[N_NODES * 6 * C];     // v[n,k,d]
__device__ __align__(128) float g_coef[NL * N_EDGES * 8]; // edge MLP coefs, padded
__device__ float g_stats[2 * C];                          // BN sum / sumsq

// ---- packed fp32x2 helpers (sm_103a) ----
__device__ __forceinline__ void fma2(unsigned long long& acc, unsigned long long a,
                                     unsigned long long b) {
    asm("fma.rn.f32x2 %0, %1, %2, %0;" : "+l"(acc) : "l"(a), "l"(b));
}
__device__ __forceinline__ unsigned long long pack2(float v) {
    unsigned long long r;
    asm("mov.b64 %0, {%1, %1};" : "=l"(r) : "f"(v));
    return r;
}
__device__ __forceinline__ void red_add_v4(float* addr, float4 v) {
    asm volatile("red.global.add.v4.f32 [%0], {%1, %2, %3, %4};"
                 :: "l"(addr), "f"(v.x), "f"(v.y), "f"(v.z), "f"(v.w) : "memory");
}

// ---------------------------------------------------------------------------
// h = leaky(x @ lin_W + lin_b). x staged through smem in 3 chunks of 25 cols
// (coalesced global reads, conflict-free smem stride 27). [R7 version,
// verified correct in R7's passing run.]
// ---------------------------------------------------------------------------
__global__ void __launch_bounds__(256) k_init(const float* __restrict__ x,
                                              const float* __restrict__ W,
                                              const float* __restrict__ b) {
    __shared__ __align__(16) float sW[ND * C];   // 9.6 KB
    __shared__ float sb[C];
    __shared__ float sX[256 * 27];               // 27.6 KB
    for (int i = threadIdx.x; i < ND * C; i += 256) sW[i] = W[i];
    if (threadIdx.x < C) sb[threadIdx.x] = b[threadIdx.x];

    int nodeBase = blockIdx.x * 256;
    int node = nodeBase + threadIdx.x;

    unsigned long long acc[16];
#pragma unroll
    for (int j = 0; j < 16; j++) acc[j] = 0ULL;

    for (int ch = 0; ch < 3; ch++) {
        __syncthreads();
        for (int i = threadIdx.x; i < 256 * 25; i += 256) {
            int n = i / 25, j = i % 25;
            int gn = nodeBase + n;
            sX[n * 27 + j] = (gn < N_NODES) ? x[(size_t)gn * ND + ch * 25 + j] : 0.f;
        }
        __syncthreads();
        if (node < N_NODES) {
#pragma unroll
            for (int j = 0; j < 25; j++) {
                unsigned long long p = pack2(sX[threadIdx.x * 27 + j]);
                const ulonglong2* wr = (const ulonglong2*)(sW + (ch * 25 + j) * C);
#pragma unroll
                for (int q = 0; q < 8; q++) {
                    ulonglong2 w = wr[q];
                    fma2(acc[2 * q], p, w.x);
                    fma2(acc[2 * q + 1], p, w.y);
                }
            }
        }
    }
    if (node >= N_NODES) return;
    const float* af = (const float*)acc;
    float4* ho = (float4*)(g_h + (size_t)node * C);
#pragma unroll
    for (int q = 0; q < 8; q++) {
        float a0 = af[4 * q] + sb[4 * q];
        float a1 = af[4 * q + 1] + sb[4 * q + 1];
        float a2 = af[4 * q + 2] + sb[4 * q + 2];
        float a3 = af[4 * q + 3] + sb[4 * q + 3];
        float4 v;
        v.x = a0 > 0.f ? a0 : 0.01f * a0;
        v.y = a1 > 0.f ? a1 : 0.01f * a1;
        v.z = a2 > 0.f ? a2 : 0.01f * a2;
        v.w = a3 > 0.f ? a3 : 0.01f * a3;
        ho[q] = v;
    }
}

// ---------------------------------------------------------------------------
// Precompute edge-MLP coefs for ALL layers (edge_attr is layer-invariant).
// ---------------------------------------------------------------------------
__global__ void __launch_bounds__(256) k_coef(const float* __restrict__ ea,
                                              const float* __restrict__ W1,
                                              const float* __restrict__ b1) {
    __shared__ float sW1[NL * ED * HID];
    __shared__ float sb1[NL * HID];
    if (threadIdx.x < NL * ED * HID) sW1[threadIdx.x] = W1[threadIdx.x];
    if (threadIdx.x < NL * HID) sb1[threadIdx.x] = b1[threadIdx.x];
    __syncthreads();
    int e = blockIdx.x * blockDim.x + threadIdx.x;
    if (e >= N_EDGES) return;
    float eav[ED];
    const float4* ear = (const float4*)(ea + (size_t)e * ED);
#pragma unroll
    for (int q = 0; q < 3; q++) {
        float4 v = ear[q];
        eav[4 * q] = v.x; eav[4 * q + 1] = v.y; eav[4 * q + 2] = v.z; eav[4 * q + 3] = v.w;
    }
#pragma unroll
    for (int l = 0; l < NL; l++) {
        float out[8];
#pragma unroll
        for (int k = 0; k < HID; k++) {
            float s = sb1[l * HID + k];
#pragma unroll
            for (int j = 0; j < ED; j++) s += eav[j] * sW1[(l * ED + j) * HID + k];
            out[k] = fmaxf(s, 0.f);
        }
        out[5] = 1.f; out[6] = 0.f; out[7] = 0.f;
        float4* co = (float4*)(g_coef + ((size_t)l * N_EDGES + e) * 8);
        co[0] = make_float4(out[0], out[1], out[2], out[3]);
        co[1] = make_float4(out[4], out[5], out[6], out[7]);
    }
}

// ---------------------------------------------------------------------------
// k_v (R6 verbatim — best measured config): warp = (slot, 32 nodes), lane=node.
//   0..4: h @ W2[k] -> g_v ; 5: h @ b2 -> g_v ; 6: h @ rootW + cb -> g_agg
// Layers >0 compute h inline: BN(prev stats)+leaky on g_agg. Broadcast weight
// LDS amortized over 32 nodes/warp — the crossbar-optimal layout.
// ---------------------------------------------------------------------------
__global__ void __launch_bounds__(256) k_v(const float* __restrict__ W2,
                                           const float* __restrict__ b2,
                                           const float* __restrict__ rootW,
                                           const float* __restrict__ cb,
                                           const float* __restrict__ bng,
                                           const float* __restrict__ bnb,
                                           int first) {
    __shared__ __align__(16) float sW[7 * C * C];   // 28 KB
    __shared__ float snorm[4 * C];
    __shared__ float scb[C];
    for (int i = threadIdx.x; i < HID * C * C; i += 256) sW[i] = W2[i];
    for (int i = threadIdx.x; i < C * C; i += 256) {
        sW[5 * C * C + i] = b2[i];
        sW[6 * C * C + i] = rootW[i];
    }
    if (threadIdx.x < C) {
        scb[threadIdx.x] = cb[threadIdx.x];
        if (!first) {
            float mu = g_stats[threadIdx.x] * (1.0f / N_NODES);
            float var = g_stats[C + threadIdx.x] * (1.0f / N_NODES) - mu * mu;
            snorm[threadIdx.x] = mu;
            snorm[C + threadIdx.x] = rsqrtf(var + BN_EPS);
            snorm[2 * C + threadIdx.x] = bng[threadIdx.x];
            snorm[3 * C + threadIdx.x] = bnb[threadIdx.x];
        }
    }
    __syncthreads();

    int gw = blockIdx.x * 8 + (threadIdx.x >> 5);
    int slot = gw % 7;
    int node = (gw / 7) * 32 + (threadIdx.x & 31);
    if (node >= N_NODES) return;

    float h[C];
    if (first) {
        const float4* hp = (const float4*)(g_h + (size_t)node * C);
#pragma unroll
        for (int q = 0; q < 8; q++) {
            float4 v = hp[q];
            h[4 * q] = v.x; h[4 * q + 1] = v.y; h[4 * q + 2] = v.z; h[4 * q + 3] = v.w;
        }
    } else {
        const float4* ap = (const float4*)(g_agg + (size_t)node * C);
#pragma unroll
        for (int q = 0; q < 8; q++) {
            float4 v = ap[q];
            float t[4] = {v.x, v.y, v.z, v.w};
#pragma unroll
            for (int r = 0; r < 4; r++) {
                int c = 4 * q + r;
                float val = (t[r] - snorm[c]) * snorm[C + c] * snorm[2 * C + c] + snorm[3 * C + c];
                h[c] = val > 0.f ? val : 0.01f * val;
            }
        }
    }

    unsigned long long acc[16];
#pragma unroll
    for (int j = 0; j < 16; j++) acc[j] = 0ULL;
    const float* wbase = sW + slot * C * C;
#pragma unroll 8
    for (int c = 0; c < C; c++) {
        unsigned long long p = pack2(h[c]);
        const ulonglong2* wr = (const ulonglong2*)(wbase + c * C);
#pragma unroll
        for (int j = 0; j < 8; j++) {
            ulonglong2 w = wr[j];
            fma2(acc[2 * j], p, w.x);
            fma2(acc[2 * j + 1], p, w.y);
        }
    }

    if (slot == 6) {
        float4* ao = (float4*)(g_agg + (size_t)node * C);
        const float* af = (const float*)acc;
#pragma unroll
        for (int q = 0; q < 8; q++) {
            float4 v;
            v.x = af[4 * q] + scb[4 * q];
            v.y = af[4 * q + 1] + scb[4 * q + 1];
            v.z = af[4 * q + 2] + scb[4 * q + 2];
            v.w = af[4 * q + 3] + scb[4 * q + 3];
            ao[q] = v;
        }
    } else {
        float4* vo = (float4*)(g_v + (size_t)node * (6 * C) + slot * C);
        const float4* af = (const float4*)acc;
#pragma unroll
        for (int q = 0; q < 8; q++) vo[q] = af[q];
    }
}

// ---------------------------------------------------------------------------
// Edge kernel (unchanged, measured 17us): 8 lanes per edge (warp = 4 edges).
// Block 0 zeroes g_stats for this layer's k_stats.
// ---------------------------------------------------------------------------
__global__ void __launch_bounds__(256) k_edge(const int* __restrict__ src,
                                              const int* __restrict__ dst,
                                              int layer) {
    if (blockIdx.x == 0 && threadIdx.x < 2 * C) g_stats[threadIdx.x] = 0.f;

    const float* coefL = g_coef + (size_t)layer * N_EDGES * 8;

    int lane = threadIdx.x & 31;
    int warp = (blockIdx.x * blockDim.x + threadIdx.x) >> 5;
    int group = lane >> 3;
    int d4 = lane & 7;
    int e = warp * 4 + group;
    if (e >= N_EDGES) return;

    int sn = __ldg(src + e);
    int dn = __ldg(dst + e);
    const float* cp = coefL + (size_t)e * 8;
    float4 c03 = __ldg((const float4*)cp);
    float2 c45 = __ldg((const float2*)(cp + 4));
    float coef[6] = {c03.x, c03.y, c03.z, c03.w, c45.x, c45.y};

    unsigned long long a0 = 0ULL, a1 = 0ULL;
    const float* vb = g_v + (size_t)sn * (6 * C) + d4 * 4;
#pragma unroll
    for (int k = 0; k < 6; k++) {
        float ck = coef[k];
        if (ck != 0.f) {
            ulonglong2 w = __ldg((const ulonglong2*)(vb + k * C));
            unsigned long long p = pack2(ck);
            fma2(a0, p, w.x);
            fma2(a1, p, w.y);
        }
    }

    float2 lo = *(float2*)&a0, hi = *(float2*)&a1;
    red_add_v4(g_agg + (size_t)dn * C + d4 * 4, make_float4(lo.x, lo.y, hi.x, hi.y));
}

// ---------------------------------------------------------------------------
// BN statistics over g_agg, MLP-optimized: 5 unconditional + 1 guarded
// independent LDG.128 per thread (grid MUST be 296 blocks; stride 75776 ≡ 0
// mod 8 keeps each lane on a fixed channel group). On the last layer, blocks
// 0-1 also seed out with pred_b.
// ---------------------------------------------------------------------------
#define STAT_STRIDE (296 * 256)

__global__ void __launch_bounds__(256) k_stats(float* out, const float* __restrict__ pb,
                                               int do_out) {
    if (do_out && blockIdx.x < 2) {
        int g = blockIdx.x * 256 + threadIdx.x;
        if (g < NG) out[g] = pb[0];
    }
    __shared__ float ss[2 * C];
    if (threadIdx.x < 2 * C) ss[threadIdx.x] = 0.f;
    __syncthreads();

    const float4* A = (const float4*)g_agg;
    int base = blockIdx.x * 256 + threadIdx.x;
    // N_NODES*8 = 400000; base + 4*STAT_STRIDE <= 75775 + 303104 = 378879 < 400000
    float4 v0 = A[base];
    float4 v1 = A[base + STAT_STRIDE];
    float4 v2 = A[base + 2 * STAT_STRIDE];
    float4 v3 = A[base + 3 * STAT_STRIDE];
    float4 v4 = A[base + 4 * STAT_STRIDE];
    float4 s, q;
    s.x = v0.x + v1.x + v2.x + v3.x + v4.x;
    s.y = v0.y + v1.y + v2.y + v3.y + v4.y;
    s.z = v0.z + v1.z + v2.z + v3.z + v4.z;
    s.w = v0.w + v1.w + v2.w + v3.w + v4.w;
    q.x = v0.x * v0.x + v1.x * v1.x + v2.x * v2.x + v3.x * v3.x + v4.x * v4.x;
    q.y = v0.y * v0.y + v1.y * v1.y + v2.y * v2.y + v3.y * v3.y + v4.y * v4.y;
    q.z = v0.z * v0.z + v1.z * v1.z + v2.z * v2.z + v3.z * v3.z + v4.z * v4.z;
    q.w = v0.w * v0.w + v1.w * v1.w + v2.w * v2.w + v3.w * v3.w + v4.w * v4.w;
    int i5 = base + 5 * STAT_STRIDE;
    if (i5 < N_NODES * 8) {
        float4 v5 = A[i5];
        s.x += v5.x; s.y += v5.y; s.z += v5.z; s.w += v5.w;
        q.x += v5.x * v5.x; q.y += v5.y * v5.y; q.z += v5.z * v5.z; q.w += v5.w * v5.w;
    }

#pragma unroll
    for (int off = 8; off <= 16; off <<= 1) {
        s.x += __shfl_xor_sync(0xffffffffu, s.x, off);
        s.y += __shfl_xor_sync(0xffffffffu, s.y, off);
        s.z += __shfl_xor_sync(0xffffffffu, s.z, off);
        s.w += __shfl_xor_sync(0xffffffffu, s.w, off);
        q.x += __shfl_xor_sync(0xffffffffu, q.x, off);
        q.y += __shfl_xor_sync(0xffffffffu, q.y, off);
        q.z += __shfl_xor_sync(0xffffffffu, q.z, off);
        q.w += __shfl_xor_sync(0xffffffffu, q.w, off);
    }
    int lane = threadIdx.x & 31;
    if (lane < 8) {
        int cg = lane * 4;
        atomicAdd(&ss[cg + 0], s.x); atomicAdd(&ss[cg + 1], s.y);
        atomicAdd(&ss[cg + 2], s.z); atomicAdd(&ss[cg + 3], s.w);
        atomicAdd(&ss[C + cg + 0], q.x); atomicAdd(&ss[C + cg + 1], q.y);
        atomicAdd(&ss[C + cg + 2], q.z); atomicAdd(&ss[C + cg + 3], q.w);
    }
    __syncthreads();
    if (threadIdx.x < 2 * C) atomicAdd(&g_stats[threadIdx.x], ss[threadIdx.x]);
}

// ---------------------------------------------------------------------------
// Final: BN (no leaky) + prediction dot + scatter to graphs (batch is sorted).
// Tail lanes clamp and contribute 0 (all collectives full-warp).
// ---------------------------------------------------------------------------
__global__ void __launch_bounds__(256) k_fin(const int* __restrict__ batch,
                                             const float* __restrict__ pW,
                                             const float* __restrict__ bng,
                                             const float* __restrict__ bnb,
                                             float* out) {
    __shared__ float snorm[4 * C];
    __shared__ float spw[C];
    if (threadIdx.x < C) {
        float mu = g_stats[threadIdx.x] * (1.0f / N_NODES);
        float var = g_stats[C + threadIdx.x] * (1.0f / N_NODES) - mu * mu;
        snorm[threadIdx.x] = mu;
        snorm[C + threadIdx.x] = rsqrtf(var + BN_EPS);
        snorm[2 * C + threadIdx.x] = bng[threadIdx.x];
        snorm[3 * C + threadIdx.x] = bnb[threadIdx.x];
        spw[threadIdx.x] = pW[threadIdx.x];
    }
    __syncthreads();
    int n = blockIdx.x * blockDim.x + threadIdx.x;
    bool valid = n < N_NODES;
    int nn = valid ? n : N_NODES - 1;
    const float4* ap = (const float4*)(g_agg + (size_t)nn * C);
    float s = 0.f;
#pragma unroll
    for (int q = 0; q < 8; q++) {
        float4 v = ap[q];
        float t[4] = {v.x, v.y, v.z, v.w};
#pragma unroll
        for (int r = 0; r < 4; r++) {
            int c = 4 * q + r;
            float val = (t[r] - snorm[c]) * snorm[C + c] * snorm[2 * C + c] + snorm[3 * C + c];
            s += val * spw[c];
        }
    }
    if (!valid) s = 0.f;
    int bid = batch[nn];
    int bid0 = __shfl_sync(0xffffffffu, bid, 0);
    bool uni = __all_sync(0xffffffffu, bid == bid0 && valid);
    if (uni) {
#pragma unroll
        for (int off = 16; off >= 1; off >>= 1)
            s += __shfl_xor_sync(0xffffffffu, s, off);
        if ((threadIdx.x & 31) == 0) atomicAdd(&out[bid0], s);
    } else if (valid) {
        atomicAdd(&out[bid], s);
    }
}

// ---------------------------------------------------------------------------
extern "C" void kernel_launch(void* const* d_in, const int* in_sizes, int n_in,
                              void* d_out, int out_size) {
    const float* x       = (const float*)d_in[0];
    const int*   ei      = (const int*)d_in[1];
    const float* ea      = (const float*)d_in[2];
    const int*   batch   = (const int*)d_in[3];
    const float* lin_W   = (const float*)d_in[4];
    const float* lin_b   = (const float*)d_in[5];
    const float* mes_W1  = (const float*)d_in[6];
    const float* mes_b1  = (const float*)d_in[7];
    const float* mes_W2  = (const float*)d_in[8];
    const float* mes_b2  = (const float*)d_in[9];
    const float* root_W  = (const float*)d_in[10];
    const float* conv_b  = (const float*)d_in[11];
    const float* bn_g    = (const float*)d_in[12];
    const float* bn_b    = (const float*)d_in[13];
    const float* pred_W  = (const float*)d_in[14];
    const float* pred_b  = (const float*)d_in[15];
    float* out = (float*)d_out;

    const int* src = ei;
    const int* dst = ei + N_EDGES;

    int vwarps = 7 * ((N_NODES + 31) / 32);
    int vblocks = (vwarps + 7) / 8;                  // 1368
    int eblocks = (N_EDGES / 4 * 32 + 255) / 256;    // 6250

    k_init<<<(N_NODES + 255) / 256, 256>>>(x, lin_W, lin_b);
    k_coef<<<(N_EDGES + 255) / 256, 256>>>(ea, mes_W1, mes_b1);
    for (int l = 0; l < NL; l++) {
        k_v<<<vblocks, 256>>>(mes_W2 + l * HID * C * C, mes_b2 + l * C * C,
                              root_W + l * C * C, conv_b + l * C,
                              l > 0 ? bn_g + (l - 1) * C : bn_g,
                              l > 0 ? bn_b + (l - 1) * C : bn_b,
                              l == 0 ? 1 : 0);
        k_edge<<<eblocks, 256>>>(src, dst, l);
        k_stats<<<296, 256>>>(out, pred_b, l == NL - 1 ? 1 : 0);
    }
    k_fin<<<(N_NODES + 255) / 256, 256>>>(batch, pred_W, bn_g + 2 * C, bn_b + 2 * C, out);
}

// round 13
// speedup vs baseline: 1.3436x; 1.2155x over previous
#include <cuda_runtime.h>

#define N_NODES 50000
#define N_EDGES 200000
#define C 32
#define ND 75
#define ED 12
#define NL 3
#define NG 500
#define HID 5
#define BN_EPS 1e-5f

// Scratch (no allocations allowed)
__device__ __align__(128) float g_h[N_NODES * C];         // layer-0 features
__device__ __align__(128) float g_agg[N_NODES * C];       // conv accumulator
__device__ __align__(128) float g_v[N_NODES * 6 * C];     // v[n,k,d]
__device__ __align__(128) float g_coef[NL * N_EDGES * 8]; // edge MLP coefs, padded
__device__ float g_stats[2 * C];                          // BN sum / sumsq

// ---- packed fp32x2 helpers (sm_103a) ----
__device__ __forceinline__ void fma2(unsigned long long& acc, unsigned long long a,
                                     unsigned long long b) {
    asm("fma.rn.f32x2 %0, %1, %2, %0;" : "+l"(acc) : "l"(a), "l"(b));
}
__device__ __forceinline__ unsigned long long pack2(float v) {
    unsigned long long r;
    asm("mov.b64 %0, {%1, %1};" : "=l"(r) : "f"(v));
    return r;
}
__device__ __forceinline__ void red_add_v4(float* addr, float4 v) {
    asm volatile("red.global.add.v4.f32 [%0], {%1, %2, %3, %4};"
                 :: "l"(addr), "f"(v.x), "f"(v.y), "f"(v.z), "f"(v.w) : "memory");
}

// ---------------------------------------------------------------------------
// h = leaky(x @ lin_W + lin_b)   (R6 baseline version — known-good)
// ---------------------------------------------------------------------------
__global__ void __launch_bounds__(256) k_init(const float* __restrict__ x,
                                              const float* __restrict__ W,
                                              const float* __restrict__ b) {
    __shared__ __align__(16) float sW[ND * C];
    __shared__ float sb[C];
    for (int i = threadIdx.x; i < ND * C; i += blockDim.x) sW[i] = W[i];
    if (threadIdx.x < C) sb[threadIdx.x] = b[threadIdx.x];
    __syncthreads();
    int n = blockIdx.x * blockDim.x + threadIdx.x;
    if (n >= N_NODES) return;
    float acc[C];
#pragma unroll
    for (int d = 0; d < C; d++) acc[d] = sb[d];
    const float* xr = x + (size_t)n * ND;
#pragma unroll 5
    for (int j = 0; j < ND; j++) {
        float xv = __ldg(xr + j);
#pragma unroll
        for (int d = 0; d < C; d++) acc[d] += xv * sW[j * C + d];
    }
    float4* ho = (float4*)(g_h + (size_t)n * C);
#pragma unroll
    for (int q = 0; q < 8; q++) {
        float4 v;
        float a0 = acc[4 * q], a1 = acc[4 * q + 1], a2 = acc[4 * q + 2], a3 = acc[4 * q + 3];
        v.x = a0 > 0.f ? a0 : 0.01f * a0;
        v.y = a1 > 0.f ? a1 : 0.01f * a1;
        v.z = a2 > 0.f ? a2 : 0.01f * a2;
        v.w = a3 > 0.f ? a3 : 0.01f * a3;
        ho[q] = v;
    }
}

// ---------------------------------------------------------------------------
// Precompute edge-MLP coefs for ALL layers (edge_attr is layer-invariant).
// ---------------------------------------------------------------------------
__global__ void __launch_bounds__(256) k_coef(const float* __restrict__ ea,
                                              const float* __restrict__ W1,
                                              const float* __restrict__ b1) {
    __shared__ float sW1[NL * ED * HID];
    __shared__ float sb1[NL * HID];
    if (threadIdx.x < NL * ED * HID) sW1[threadIdx.x] = W1[threadIdx.x];
    if (threadIdx.x < NL * HID) sb1[threadIdx.x] = b1[threadIdx.x];
    __syncthreads();
    int e = blockIdx.x * blockDim.x + threadIdx.x;
    if (e >= N_EDGES) return;
    float eav[ED];
    const float4* ear = (const float4*)(ea + (size_t)e * ED);
#pragma unroll
    for (int q = 0; q < 3; q++) {
        float4 v = ear[q];
        eav[4 * q] = v.x; eav[4 * q + 1] = v.y; eav[4 * q + 2] = v.z; eav[4 * q + 3] = v.w;
    }
#pragma unroll
    for (int l = 0; l < NL; l++) {
        float out[8];
#pragma unroll
        for (int k = 0; k < HID; k++) {
            float s = sb1[l * HID + k];
#pragma unroll
            for (int j = 0; j < ED; j++) s += eav[j] * sW1[(l * ED + j) * HID + k];
            out[k] = fmaxf(s, 0.f);
        }
        out[5] = 1.f; out[6] = 0.f; out[7] = 0.f;
        float4* co = (float4*)(g_coef + ((size_t)l * N_EDGES + e) * 8);
        co[0] = make_float4(out[0], out[1], out[2], out[3]);
        co[1] = make_float4(out[4], out[5], out[6], out[7]);
    }
}

// ---------------------------------------------------------------------------
// k_v: R6 structure with ONE change — h staged through smem.
// Block's 8 warps span <=2 node-groups (gw = b*8..b*8+7, group = gw/7).
// Cooperative phase: load 64 h rows coalesced (float4), BN+leaky applied once,
// into sH at padded stride 36 (conflict-free LDS.128 reads: 36 mod 32 = 4).
// Compute phase: identical to R6 (warp = slot x 32 nodes, broadcast weight
// LDS), but h comes from sH via 8 LDS.128 (32 l1tex cycles vs 256 wavefronts).
// ---------------------------------------------------------------------------
__global__ void __launch_bounds__(256) k_v(const float* __restrict__ W2,
                                           const float* __restrict__ b2,
                                           const float* __restrict__ rootW,
                                           const float* __restrict__ cb,
                                           const float* __restrict__ bng,
                                           const float* __restrict__ bnb,
                                           int first) {
    __shared__ __align__(16) float sW[7 * C * C];   // 28 KB
    __shared__ __align__(16) float sH[64 * 36];     // 9 KB (stride 36)
    __shared__ float snorm[2 * C];                  // fused scale/shift
    __shared__ float scb[C];
    for (int i = threadIdx.x; i < HID * C * C; i += 256) sW[i] = W2[i];
    for (int i = threadIdx.x; i < C * C; i += 256) {
        sW[5 * C * C + i] = b2[i];
        sW[6 * C * C + i] = rootW[i];
    }
    if (threadIdx.x < C) {
        scb[threadIdx.x] = cb[threadIdx.x];
        if (!first) {
            float mu = g_stats[threadIdx.x] * (1.0f / N_NODES);
            float var = g_stats[C + threadIdx.x] * (1.0f / N_NODES) - mu * mu;
            float Av = rsqrtf(var + BN_EPS) * bng[threadIdx.x];
            snorm[threadIdx.x] = Av;                            // scale
            snorm[C + threadIdx.x] = bnb[threadIdx.x] - mu * Av; // shift
        }
    }
    __syncthreads();

    int b8 = blockIdx.x * 8;
    int g0 = b8 / 7;                 // first node-group this block touches
    int nodeBase = g0 * 32;
    const float* hin = first ? g_h : g_agg;

    // Cooperative h load: 64 rows x 8 float4 chunks, coalesced.
    for (int i = threadIdx.x; i < 64 * 8; i += 256) {
        int r = i >> 3, q = i & 7;
        int n = nodeBase + r;
        if (n < N_NODES) {
            float4 v = ((const float4*)(hin + (size_t)n * C))[q];
            if (!first) {
                int c0 = q * 4;
                v.x = v.x * snorm[c0] + snorm[C + c0];
                v.x = v.x > 0.f ? v.x : 0.01f * v.x;
                v.y = v.y * snorm[c0 + 1] + snorm[C + c0 + 1];
                v.y = v.y > 0.f ? v.y : 0.01f * v.y;
                v.z = v.z * snorm[c0 + 2] + snorm[C + c0 + 2];
                v.z = v.z > 0.f ? v.z : 0.01f * v.z;
                v.w = v.w * snorm[c0 + 3] + snorm[C + c0 + 3];
                v.w = v.w > 0.f ? v.w : 0.01f * v.w;
            }
            *(float4*)&sH[r * 36 + q * 4] = v;
        }
    }
    __syncthreads();

    int gw = b8 + (threadIdx.x >> 5);
    int slot = gw % 7;
    int grp = gw / 7;
    int lane = threadIdx.x & 31;
    int node = grp * 32 + lane;
    if (node >= N_NODES) return;

    const float* hrow = sH + ((grp - g0) * 32 + lane) * 36;
    unsigned long long acc[16];
#pragma unroll
    for (int j = 0; j < 16; j++) acc[j] = 0ULL;
    const float* wbase = sW + slot * C * C;

#pragma unroll
    for (int q8 = 0; q8 < 8; q8++) {
        float4 hv = *(const float4*)(hrow + q8 * 4);    // conflict-free LDS.128
        float hc[4] = {hv.x, hv.y, hv.z, hv.w};
#pragma unroll
        for (int r = 0; r < 4; r++) {
            unsigned long long p = pack2(hc[r]);
            const ulonglong2* wr = (const ulonglong2*)(wbase + (q8 * 4 + r) * C);
#pragma unroll
            for (int j = 0; j < 8; j++) {
                ulonglong2 w = wr[j];
                fma2(acc[2 * j], p, w.x);
                fma2(acc[2 * j + 1], p, w.y);
            }
        }
    }

    if (slot == 6) {
        float4* ao = (float4*)(g_agg + (size_t)node * C);
        const float* af = (const float*)acc;
#pragma unroll
        for (int q = 0; q < 8; q++) {
            float4 v;
            v.x = af[4 * q] + scb[4 * q];
            v.y = af[4 * q + 1] + scb[4 * q + 1];
            v.z = af[4 * q + 2] + scb[4 * q + 2];
            v.w = af[4 * q + 3] + scb[4 * q + 3];
            ao[q] = v;
        }
    } else {
        float4* vo = (float4*)(g_v + (size_t)node * (6 * C) + slot * C);
        const float4* af = (const float4*)acc;
#pragma unroll
        for (int q = 0; q < 8; q++) vo[q] = af[q];
    }
}

// ---------------------------------------------------------------------------
// Edge kernel (R6 verbatim, measured 17us): 8 lanes per edge (warp = 4 edges).
// Block 0 zeroes g_stats for this layer's k_stats.
// ---------------------------------------------------------------------------
__global__ void __launch_bounds__(256) k_edge(const int* __restrict__ src,
                                              const int* __restrict__ dst,
                                              int layer) {
    if (blockIdx.x == 0 && threadIdx.x < 2 * C) g_stats[threadIdx.x] = 0.f;

    const float* coefL = g_coef + (size_t)layer * N_EDGES * 8;

    int lane = threadIdx.x & 31;
    int warp = (blockIdx.x * blockDim.x + threadIdx.x) >> 5;
    int group = lane >> 3;
    int d4 = lane & 7;
    int e = warp * 4 + group;
    if (e >= N_EDGES) return;

    int sn = __ldg(src + e);
    int dn = __ldg(dst + e);
    const float* cp = coefL + (size_t)e * 8;
    float4 c03 = __ldg((const float4*)cp);
    float2 c45 = __ldg((const float2*)(cp + 4));
    float coef[6] = {c03.x, c03.y, c03.z, c03.w, c45.x, c45.y};

    unsigned long long a0 = 0ULL, a1 = 0ULL;
    const float* vb = g_v + (size_t)sn * (6 * C) + d4 * 4;
#pragma unroll
    for (int k = 0; k < 6; k++) {
        float ck = coef[k];
        if (ck != 0.f) {
            ulonglong2 w = __ldg((const ulonglong2*)(vb + k * C));
            unsigned long long p = pack2(ck);
            fma2(a0, p, w.x);
            fma2(a1, p, w.y);
        }
    }

    float2 lo = *(float2*)&a0, hi = *(float2*)&a1;
    red_add_v4(g_agg + (size_t)dn * C + d4 * 4, make_float4(lo.x, lo.y, hi.x, hi.y));
}

// ---------------------------------------------------------------------------
// BN statistics: per-channel sum / sumsq over g_agg.  (R6 verbatim)
// ---------------------------------------------------------------------------
__global__ void __launch_bounds__(256) k_stats() {
    __shared__ float ss[2 * C];
    if (threadIdx.x < 2 * C) ss[threadIdx.x] = 0.f;
    __syncthreads();
    const float4* A = (const float4*)g_agg;
    float4 s = {0.f, 0.f, 0.f, 0.f}, q = {0.f, 0.f, 0.f, 0.f};
    int stride = gridDim.x * blockDim.x;
    for (int i = blockIdx.x * blockDim.x + threadIdx.x; i < N_NODES * 8; i += stride) {
        float4 v = A[i];
        s.x += v.x; s.y += v.y; s.z += v.z; s.w += v.w;
        q.x += v.x * v.x; q.y += v.y * v.y; q.z += v.z * v.z; q.w += v.w * v.w;
    }
#pragma unroll
    for (int off = 8; off <= 16; off <<= 1) {
        s.x += __shfl_xor_sync(0xffffffffu, s.x, off);
        s.y += __shfl_xor_sync(0xffffffffu, s.y, off);
        s.z += __shfl_xor_sync(0xffffffffu, s.z, off);
        s.w += __shfl_xor_sync(0xffffffffu, s.w, off);
        q.x += __shfl_xor_sync(0xffffffffu, q.x, off);
        q.y += __shfl_xor_sync(0xffffffffu, q.y, off);
        q.z += __shfl_xor_sync(0xffffffffu, q.z, off);
        q.w += __shfl_xor_sync(0xffffffffu, q.w, off);
    }
    int lane = threadIdx.x & 31;
    if (lane < 8) {
        int cg = lane * 4;
        atomicAdd(&ss[cg + 0], s.x); atomicAdd(&ss[cg + 1], s.y);
        atomicAdd(&ss[cg + 2], s.z); atomicAdd(&ss[cg + 3], s.w);
        atomicAdd(&ss[C + cg + 0], q.x); atomicAdd(&ss[C + cg + 1], q.y);
        atomicAdd(&ss[C + cg + 2], q.z); atomicAdd(&ss[C + cg + 3], q.w);
    }
    __syncthreads();
    if (threadIdx.x < 2 * C) atomicAdd(&g_stats[threadIdx.x], ss[threadIdx.x]);
}

// ---------------------------------------------------------------------------
// Final: BN (no leaky) + prediction dot + scatter to graphs (batch is sorted).
// (R6 verbatim)
// ---------------------------------------------------------------------------
__global__ void k_out_init(const float* __restrict__ pb, float* out) {
    int g = blockIdx.x * blockDim.x + threadIdx.x;
    if (g < NG) out[g] = pb[0];
}

__global__ void __launch_bounds__(256) k_fin(const int* __restrict__ batch,
                                             const float* __restrict__ pW,
                                             const float* __restrict__ bng,
                                             const float* __restrict__ bnb,
                                             float* out) {
    __shared__ float snorm[4 * C];
    __shared__ float spw[C];
    if (threadIdx.x < C) {
        float mu = g_stats[threadIdx.x] * (1.0f / N_NODES);
        float var = g_stats[C + threadIdx.x] * (1.0f / N_NODES) - mu * mu;
        snorm[threadIdx.x] = mu;
        snorm[C + threadIdx.x] = rsqrtf(var + BN_EPS);
        snorm[2 * C + threadIdx.x] = bng[threadIdx.x];
        snorm[3 * C + threadIdx.x] = bnb[threadIdx.x];
        spw[threadIdx.x] = pW[threadIdx.x];
    }
    __syncthreads();
    int n = blockIdx.x * blockDim.x + threadIdx.x;
    bool valid = n < N_NODES;
    int nn = valid ? n : N_NODES - 1;
    const float4* ap = (const float4*)(g_agg + (size_t)nn * C);
    float s = 0.f;
#pragma unroll
    for (int q = 0; q < 8; q++) {
        float4 v = ap[q];
        float t[4] = {v.x, v.y, v.z, v.w};
#pragma unroll
        for (int r = 0; r < 4; r++) {
            int c = 4 * q + r;
            float val = (t[r] - snorm[c]) * snorm[C + c] * snorm[2 * C + c] + snorm[3 * C + c];
            s += val * spw[c];
        }
    }
    if (!valid) s = 0.f;
    int bid = batch[nn];
    int bid0 = __shfl_sync(0xffffffffu, bid, 0);
    bool uni = __all_sync(0xffffffffu, bid == bid0 && valid);
    if (uni) {
#pragma unroll
        for (int off = 16; off >= 1; off >>= 1)
            s += __shfl_xor_sync(0xffffffffu, s, off);
        if ((threadIdx.x & 31) == 0) atomicAdd(&out[bid0], s);
    } else if (valid) {
        atomicAdd(&out[bid], s);
    }
}

// ---------------------------------------------------------------------------
extern "C" void kernel_launch(void* const* d_in, const int* in_sizes, int n_in,
                              void* d_out, int out_size) {
    const float* x       = (const float*)d_in[0];
    const int*   ei      = (const int*)d_in[1];
    const float* ea      = (const float*)d_in[2];
    const int*   batch   = (const int*)d_in[3];
    const float* lin_W   = (const float*)d_in[4];
    const float* lin_b   = (const float*)d_in[5];
    const float* mes_W1  = (const float*)d_in[6];
    const float* mes_b1  = (const float*)d_in[7];
    const float* mes_W2  = (const float*)d_in[8];
    const float* mes_b2  = (const float*)d_in[9];
    const float* root_W  = (const float*)d_in[10];
    const float* conv_b  = (const float*)d_in[11];
    const float* bn_g    = (const float*)d_in[12];
    const float* bn_b    = (const float*)d_in[13];
    const float* pred_W  = (const float*)d_in[14];
    const float* pred_b  = (const float*)d_in[15];
    float* out = (float*)d_out;

    const int* src = ei;
    const int* dst = ei + N_EDGES;

    int vwarps = 7 * ((N_NODES + 31) / 32);
    int vblocks = (vwarps + 7) / 8;                  // 1368
    int eblocks = (N_EDGES / 4 * 32 + 255) / 256;    // 6250

    k_init<<<(N_NODES + 255) / 256, 256>>>(x, lin_W, lin_b);
    k_coef<<<(N_EDGES + 255) / 256, 256>>>(ea, mes_W1, mes_b1);
    for (int l = 0; l < NL; l++) {
        k_v<<<vblocks, 256>>>(mes_W2 + l * HID * C * C, mes_b2 + l * C * C,
                              root_W + l * C * C, conv_b + l * C,
                              l > 0 ? bn_g + (l - 1) * C : bn_g,
                              l > 0 ? bn_b + (l - 1) * C : bn_b,
                              l == 0 ? 1 : 0);
        k_edge<<<eblocks, 256>>>(src, dst, l);
        k_stats<<<1184, 256>>>();
    }
    k_out_init<<<2, 256>>>(pred_b, out);
    k_fin<<<(N_NODES + 255) / 256, 256>>>(batch, pred_W, bn_g + 2 * C, bn_b + 2 * C, out);
}

// round 14
// speedup vs baseline: 1.4344x; 1.0676x over previous
#include <cuda_runtime.h>

#define N_NODES 50000
#define N_EDGES 200000
#define C 32
#define ND 75
#define ED 12
#define NL 3
#define NG 500
#define HID 5
#define BN_EPS 1e-5f

// Scratch (no allocations allowed)
__device__ __align__(128) float g_h[N_NODES * C];         // layer-0 features
__device__ __align__(128) float g_agg[N_NODES * C];       // conv accumulator
__device__ __align__(128) float g_v[N_NODES * 6 * C];     // v[n,k,d]
__device__ __align__(128) float g_coef[NL * N_EDGES * 8]; // edge MLP coefs, padded
__device__ float g_stats[2 * C];                          // BN sum / sumsq

// ---- packed fp32x2 helpers (sm_103a) ----
__device__ __forceinline__ void fma2(unsigned long long& acc, unsigned long long a,
                                     unsigned long long b) {
    asm("fma.rn.f32x2 %0, %1, %2, %0;" : "+l"(acc) : "l"(a), "l"(b));
}
__device__ __forceinline__ unsigned long long pack2(float v) {
    unsigned long long r;
    asm("mov.b64 %0, {%1, %1};" : "=l"(r) : "f"(v));
    return r;
}
__device__ __forceinline__ void red_add_v4(float* addr, float4 v) {
    asm volatile("red.global.add.v4.f32 [%0], {%1, %2, %3, %4};"
                 :: "l"(addr), "f"(v.x), "f"(v.y), "f"(v.z), "f"(v.w) : "memory");
}

// ---------------------------------------------------------------------------
// h = leaky(x @ lin_W + lin_b)   (R6 baseline version — known-good)
// ---------------------------------------------------------------------------
__global__ void __launch_bounds__(256) k_init(const float* __restrict__ x,
                                              const float* __restrict__ W,
                                              const float* __restrict__ b) {
    __shared__ __align__(16) float sW[ND * C];
    __shared__ float sb[C];
    for (int i = threadIdx.x; i < ND * C; i += blockDim.x) sW[i] = W[i];
    if (threadIdx.x < C) sb[threadIdx.x] = b[threadIdx.x];
    __syncthreads();
    int n = blockIdx.x * blockDim.x + threadIdx.x;
    if (n >= N_NODES) return;
    float acc[C];
#pragma unroll
    for (int d = 0; d < C; d++) acc[d] = sb[d];
    const float* xr = x + (size_t)n * ND;
#pragma unroll 5
    for (int j = 0; j < ND; j++) {
        float xv = __ldg(xr + j);
#pragma unroll
        for (int d = 0; d < C; d++) acc[d] += xv * sW[j * C + d];
    }
    float4* ho = (float4*)(g_h + (size_t)n * C);
#pragma unroll
    for (int q = 0; q < 8; q++) {
        float4 v;
        float a0 = acc[4 * q], a1 = acc[4 * q + 1], a2 = acc[4 * q + 2], a3 = acc[4 * q + 3];
        v.x = a0 > 0.f ? a0 : 0.01f * a0;
        v.y = a1 > 0.f ? a1 : 0.01f * a1;
        v.z = a2 > 0.f ? a2 : 0.01f * a2;
        v.w = a3 > 0.f ? a3 : 0.01f * a3;
        ho[q] = v;
    }
}

// ---------------------------------------------------------------------------
// Precompute edge-MLP coefs for ALL layers (edge_attr is layer-invariant).
// ---------------------------------------------------------------------------
__global__ void __launch_bounds__(256) k_coef(const float* __restrict__ ea,
                                              const float* __restrict__ W1,
                                              const float* __restrict__ b1) {
    __shared__ float sW1[NL * ED * HID];
    __shared__ float sb1[NL * HID];
    if (threadIdx.x < NL * ED * HID) sW1[threadIdx.x] = W1[threadIdx.x];
    if (threadIdx.x < NL * HID) sb1[threadIdx.x] = b1[threadIdx.x];
    __syncthreads();
    int e = blockIdx.x * blockDim.x + threadIdx.x;
    if (e >= N_EDGES) return;
    float eav[ED];
    const float4* ear = (const float4*)(ea + (size_t)e * ED);
#pragma unroll
    for (int q = 0; q < 3; q++) {
        float4 v = ear[q];
        eav[4 * q] = v.x; eav[4 * q + 1] = v.y; eav[4 * q + 2] = v.z; eav[4 * q + 3] = v.w;
    }
#pragma unroll
    for (int l = 0; l < NL; l++) {
        float out[8];
#pragma unroll
        for (int k = 0; k < HID; k++) {
            float s = sb1[l * HID + k];
#pragma unroll
            for (int j = 0; j < ED; j++) s += eav[j] * sW1[(l * ED + j) * HID + k];
            out[k] = fmaxf(s, 0.f);
        }
        out[5] = 1.f; out[6] = 0.f; out[7] = 0.f;
        float4* co = (float4*)(g_coef + ((size_t)l * N_EDGES + e) * 8);
        co[0] = make_float4(out[0], out[1], out[2], out[3]);
        co[1] = make_float4(out[4], out[5], out[6], out[7]);
    }
}

// ---------------------------------------------------------------------------
// k_v (R13 version — WIN): h staged through smem; compute phase = R6 layout.
// ---------------------------------------------------------------------------
__global__ void __launch_bounds__(256) k_v(const float* __restrict__ W2,
                                           const float* __restrict__ b2,
                                           const float* __restrict__ rootW,
                                           const float* __restrict__ cb,
                                           const float* __restrict__ bng,
                                           const float* __restrict__ bnb,
                                           int first) {
    __shared__ __align__(16) float sW[7 * C * C];   // 28 KB
    __shared__ __align__(16) float sH[64 * 36];     // 9 KB (stride 36)
    __shared__ float snorm[2 * C];                  // fused scale/shift
    __shared__ float scb[C];
    for (int i = threadIdx.x; i < HID * C * C; i += 256) sW[i] = W2[i];
    for (int i = threadIdx.x; i < C * C; i += 256) {
        sW[5 * C * C + i] = b2[i];
        sW[6 * C * C + i] = rootW[i];
    }
    if (threadIdx.x < C) {
        scb[threadIdx.x] = cb[threadIdx.x];
        if (!first) {
            float mu = g_stats[threadIdx.x] * (1.0f / N_NODES);
            float var = g_stats[C + threadIdx.x] * (1.0f / N_NODES) - mu * mu;
            float Av = rsqrtf(var + BN_EPS) * bng[threadIdx.x];
            snorm[threadIdx.x] = Av;                             // scale
            snorm[C + threadIdx.x] = bnb[threadIdx.x] - mu * Av; // shift
        }
    }
    __syncthreads();

    int b8 = blockIdx.x * 8;
    int g0 = b8 / 7;                 // first node-group this block touches
    int nodeBase = g0 * 32;
    const float* hin = first ? g_h : g_agg;

    // Cooperative h load: 64 rows x 8 float4 chunks, coalesced.
    for (int i = threadIdx.x; i < 64 * 8; i += 256) {
        int r = i >> 3, q = i & 7;
        int n = nodeBase + r;
        if (n < N_NODES) {
            float4 v = ((const float4*)(hin + (size_t)n * C))[q];
            if (!first) {
                int c0 = q * 4;
                v.x = v.x * snorm[c0] + snorm[C + c0];
                v.x = v.x > 0.f ? v.x : 0.01f * v.x;
                v.y = v.y * snorm[c0 + 1] + snorm[C + c0 + 1];
                v.y = v.y > 0.f ? v.y : 0.01f * v.y;
                v.z = v.z * snorm[c0 + 2] + snorm[C + c0 + 2];
                v.z = v.z > 0.f ? v.z : 0.01f * v.z;
                v.w = v.w * snorm[c0 + 3] + snorm[C + c0 + 3];
                v.w = v.w > 0.f ? v.w : 0.01f * v.w;
            }
            *(float4*)&sH[r * 36 + q * 4] = v;
        }
    }
    __syncthreads();

    int gw = b8 + (threadIdx.x >> 5);
    int slot = gw % 7;
    int grp = gw / 7;
    int lane = threadIdx.x & 31;
    int node = grp * 32 + lane;
    if (node >= N_NODES) return;

    const float* hrow = sH + ((grp - g0) * 32 + lane) * 36;
    unsigned long long acc[16];
#pragma unroll
    for (int j = 0; j < 16; j++) acc[j] = 0ULL;
    const float* wbase = sW + slot * C * C;

#pragma unroll
    for (int q8 = 0; q8 < 8; q8++) {
        float4 hv = *(const float4*)(hrow + q8 * 4);    // conflict-free LDS.128
        float hc[4] = {hv.x, hv.y, hv.z, hv.w};
#pragma unroll
        for (int r = 0; r < 4; r++) {
            unsigned long long p = pack2(hc[r]);
            const ulonglong2* wr = (const ulonglong2*)(wbase + (q8 * 4 + r) * C);
#pragma unroll
            for (int j = 0; j < 8; j++) {
                ulonglong2 w = wr[j];
                fma2(acc[2 * j], p, w.x);
                fma2(acc[2 * j + 1], p, w.y);
            }
        }
    }

    if (slot == 6) {
        float4* ao = (float4*)(g_agg + (size_t)node * C);
        const float* af = (const float*)acc;
#pragma unroll
        for (int q = 0; q < 8; q++) {
            float4 v;
            v.x = af[4 * q] + scb[4 * q];
            v.y = af[4 * q + 1] + scb[4 * q + 1];
            v.z = af[4 * q + 2] + scb[4 * q + 2];
            v.w = af[4 * q + 3] + scb[4 * q + 3];
            ao[q] = v;
        }
    } else {
        float4* vo = (float4*)(g_v + (size_t)node * (6 * C) + slot * C);
        const float4* af = (const float4*)acc;
#pragma unroll
        for (int q = 0; q < 8; q++) vo[q] = af[q];
    }
}

// ---------------------------------------------------------------------------
// Edge kernel (R6 verbatim, measured 17us): 8 lanes per edge (warp = 4 edges).
// Block 0 zeroes g_stats for this layer's k_stats.
// ---------------------------------------------------------------------------
__global__ void __launch_bounds__(256) k_edge(const int* __restrict__ src,
                                              const int* __restrict__ dst,
                                              int layer) {
    if (blockIdx.x == 0 && threadIdx.x < 2 * C) g_stats[threadIdx.x] = 0.f;

    const float* coefL = g_coef + (size_t)layer * N_EDGES * 8;

    int lane = threadIdx.x & 31;
    int warp = (blockIdx.x * blockDim.x + threadIdx.x) >> 5;
    int group = lane >> 3;
    int d4 = lane & 7;
    int e = warp * 4 + group;
    if (e >= N_EDGES) return;

    int sn = __ldg(src + e);
    int dn = __ldg(dst + e);
    const float* cp = coefL + (size_t)e * 8;
    float4 c03 = __ldg((const float4*)cp);
    float2 c45 = __ldg((const float2*)(cp + 4));
    float coef[6] = {c03.x, c03.y, c03.z, c03.w, c45.x, c45.y};

    unsigned long long a0 = 0ULL, a1 = 0ULL;
    const float* vb = g_v + (size_t)sn * (6 * C) + d4 * 4;
#pragma unroll
    for (int k = 0; k < 6; k++) {
        float ck = coef[k];
        if (ck != 0.f) {
            ulonglong2 w = __ldg((const ulonglong2*)(vb + k * C));
            unsigned long long p = pack2(ck);
            fma2(a0, p, w.x);
            fma2(a1, p, w.y);
        }
    }

    float2 lo = *(float2*)&a0, hi = *(float2*)&a1;
    red_add_v4(g_agg + (size_t)dn * C + d4 * 4, make_float4(lo.x, lo.y, hi.x, hi.y));
}

// ---------------------------------------------------------------------------
// BN statistics, MLP/fan-in optimized (THE single change this round):
// grid MUST be 296 blocks. 5 unconditional + 1 guarded independent LDG.128
// per thread; stride 75776 ≡ 0 mod 8 keeps each lane on a fixed channel
// group. 4x fewer contended g_stats atomics than the 1184-block version.
// On the last layer, blocks 0-1 also seed out with pred_b (replaces
// k_out_init; ordered before k_fin by the stream).
// ---------------------------------------------------------------------------
#define STAT_STRIDE (296 * 256)

__global__ void __launch_bounds__(256) k_stats(float* out, const float* __restrict__ pb,
                                               int do_out) {
    if (do_out && blockIdx.x < 2) {
        int g = blockIdx.x * 256 + threadIdx.x;
        if (g < NG) out[g] = pb[0];
    }
    __shared__ float ss[2 * C];
    if (threadIdx.x < 2 * C) ss[threadIdx.x] = 0.f;
    __syncthreads();

    const float4* A = (const float4*)g_agg;
    int base = blockIdx.x * 256 + threadIdx.x;
    // N_NODES*8 = 400000; base + 4*STAT_STRIDE <= 75775 + 303104 = 378879 < 400000
    float4 v0 = A[base];
    float4 v1 = A[base + STAT_STRIDE];
    float4 v2 = A[base + 2 * STAT_STRIDE];
    float4 v3 = A[base + 3 * STAT_STRIDE];
    float4 v4 = A[base + 4 * STAT_STRIDE];
    float4 s, q;
    s.x = v0.x + v1.x + v2.x + v3.x + v4.x;
    s.y = v0.y + v1.y + v2.y + v3.y + v4.y;
    s.z = v0.z + v1.z + v2.z + v3.z + v4.z;
    s.w = v0.w + v1.w + v2.w + v3.w + v4.w;
    q.x = v0.x * v0.x + v1.x * v1.x + v2.x * v2.x + v3.x * v3.x + v4.x * v4.x;
    q.y = v0.y * v0.y + v1.y * v1.y + v2.y * v2.y + v3.y * v3.y + v4.y * v4.y;
    q.z = v0.z * v0.z + v1.z * v1.z + v2.z * v2.z + v3.z * v3.z + v4.z * v4.z;
    q.w = v0.w * v0.w + v1.w * v1.w + v2.w * v2.w + v3.w * v3.w + v4.w * v4.w;
    int i5 = base + 5 * STAT_STRIDE;
    if (i5 < N_NODES * 8) {
        float4 v5 = A[i5];
        s.x += v5.x; s.y += v5.y; s.z += v5.z; s.w += v5.w;
        q.x += v5.x * v5.x; q.y += v5.y * v5.y; q.z += v5.z * v5.z; q.w += v5.w * v5.w;
    }

#pragma unroll
    for (int off = 8; off <= 16; off <<= 1) {
        s.x += __shfl_xor_sync(0xffffffffu, s.x, off);
        s.y += __shfl_xor_sync(0xffffffffu, s.y, off);
        s.z += __shfl_xor_sync(0xffffffffu, s.z, off);
        s.w += __shfl_xor_sync(0xffffffffu, s.w, off);
        q.x += __shfl_xor_sync(0xffffffffu, q.x, off);
        q.y += __shfl_xor_sync(0xffffffffu, q.y, off);
        q.z += __shfl_xor_sync(0xffffffffu, q.z, off);
        q.w += __shfl_xor_sync(0xffffffffu, q.w, off);
    }
    int lane = threadIdx.x & 31;
    if (lane < 8) {
        int cg = lane * 4;
        atomicAdd(&ss[cg + 0], s.x); atomicAdd(&ss[cg + 1], s.y);
        atomicAdd(&ss[cg + 2], s.z); atomicAdd(&ss[cg + 3], s.w);
        atomicAdd(&ss[C + cg + 0], q.x); atomicAdd(&ss[C + cg + 1], q.y);
        atomicAdd(&ss[C + cg + 2], q.z); atomicAdd(&ss[C + cg + 3], q.w);
    }
    __syncthreads();
    if (threadIdx.x < 2 * C) atomicAdd(&g_stats[threadIdx.x], ss[threadIdx.x]);
}

// ---------------------------------------------------------------------------
// Final: BN (no leaky) + prediction dot + scatter to graphs (batch is sorted).
// (R6 verbatim)
// ---------------------------------------------------------------------------
__global__ void __launch_bounds__(256) k_fin(const int* __restrict__ batch,
                                             const float* __restrict__ pW,
                                             const float* __restrict__ bng,
                                             const float* __restrict__ bnb,
                                             float* out) {
    __shared__ float snorm[4 * C];
    __shared__ float spw[C];
    if (threadIdx.x < C) {
        float mu = g_stats[threadIdx.x] * (1.0f / N_NODES);
        float var = g_stats[C + threadIdx.x] * (1.0f / N_NODES) - mu * mu;
        snorm[threadIdx.x] = mu;
        snorm[C + threadIdx.x] = rsqrtf(var + BN_EPS);
        snorm[2 * C + threadIdx.x] = bng[threadIdx.x];
        snorm[3 * C + threadIdx.x] = bnb[threadIdx.x];
        spw[threadIdx.x] = pW[threadIdx.x];
    }
    __syncthreads();
    int n = blockIdx.x * blockDim.x + threadIdx.x;
    bool valid = n < N_NODES;
    int nn = valid ? n : N_NODES - 1;
    const float4* ap = (const float4*)(g_agg + (size_t)nn * C);
    float s = 0.f;
#pragma unroll
    for (int q = 0; q < 8; q++) {
        float4 v = ap[q];
        float t[4] = {v.x, v.y, v.z, v.w};
#pragma unroll
        for (int r = 0; r < 4; r++) {
            int c = 4 * q + r;
            float val = (t[r] - snorm[c]) * snorm[C + c] * snorm[2 * C + c] + snorm[3 * C + c];
            s += val * spw[c];
        }
    }
    if (!valid) s = 0.f;
    int bid = batch[nn];
    int bid0 = __shfl_sync(0xffffffffu, bid, 0);
    bool uni = __all_sync(0xffffffffu, bid == bid0 && valid);
    if (uni) {
#pragma unroll
        for (int off = 16; off >= 1; off >>= 1)
            s += __shfl_xor_sync(0xffffffffu, s, off);
        if ((threadIdx.x & 31) == 0) atomicAdd(&out[bid0], s);
    } else if (valid) {
        atomicAdd(&out[bid], s);
    }
}

// ---------------------------------------------------------------------------
extern "C" void kernel_launch(void* const* d_in, const int* in_sizes, int n_in,
                              void* d_out, int out_size) {
    const float* x       = (const float*)d_in[0];
    const int*   ei      = (const int*)d_in[1];
    const float* ea      = (const float*)d_in[2];
    const int*   batch   = (const int*)d_in[3];
    const float* lin_W   = (const float*)d_in[4];
    const float* lin_b   = (const float*)d_in[5];
    const float* mes_W1  = (const float*)d_in[6];
    const float* mes_b1  = (const float*)d_in[7];
    const float* mes_W2  = (const float*)d_in[8];
    const float* mes_b2  = (const float*)d_in[9];
    const float* root_W  = (const float*)d_in[10];
    const float* conv_b  = (const float*)d_in[11];
    const float* bn_g    = (const float*)d_in[12];
    const float* bn_b    = (const float*)d_in[13];
    const float* pred_W  = (const float*)d_in[14];
    const float* pred_b  = (const float*)d_in[15];
    float* out = (float*)d_out;

    const int* src = ei;
    const int* dst = ei + N_EDGES;

    int vwarps = 7 * ((N_NODES + 31) / 32);
    int vblocks = (vwarps + 7) / 8;                  // 1368
    int eblocks = (N_EDGES / 4 * 32 + 255) / 256;    // 6250

    k_init<<<(N_NODES + 255) / 256, 256>>>(x, lin_W, lin_b);
    k_coef<<<(N_EDGES + 255) / 256, 256>>>(ea, mes_W1, mes_b1);
    for (int l = 0; l < NL; l++) {
        k_v<<<vblocks, 256>>>(mes_W2 + l * HID * C * C, mes_b2 + l * C * C,
                              root_W + l * C * C, conv_b + l * C,
                              l > 0 ? bn_g + (l - 1) * C : bn_g,
                              l > 0 ? bn_b + (l - 1) * C : bn_b,
                              l == 0 ? 1 : 0);
        k_edge<<<eblocks, 256>>>(src, dst, l);
        k_stats<<<296, 256>>>(out, pred_b, l == NL - 1 ? 1 : 0);
    }
    k_fin<<<(N_NODES + 255) / 256, 256>>>(batch, pred_W, bn_g + 2 * C, bn_b + 2 * C, out);
}

// round 15
// speedup vs baseline: 1.4884x; 1.0376x over previous
#include <cuda_runtime.h>

#define N_NODES 50000
#define N_EDGES 200000
#define C 32
#define ND 75
#define ED 12
#define NL 3
#define NG 500
#define HID 5
#define BN_EPS 1e-5f

// Scratch (no allocations allowed)
__device__ __align__(128) float g_h[N_NODES * C];         // layer-0 features
__device__ __align__(128) float g_agg[N_NODES * C];       // conv accumulator
__device__ __align__(128) float g_v[N_NODES * 6 * C];     // v[n,k,d]
__device__ __align__(128) float g_coef[NL * N_EDGES * 8]; // edge MLP coefs, padded
__device__ float g_stats[2 * C];                          // BN sum / sumsq

// ---- packed fp32x2 helpers (sm_103a) ----
__device__ __forceinline__ void fma2(unsigned long long& acc, unsigned long long a,
                                     unsigned long long b) {
    asm("fma.rn.f32x2 %0, %1, %2, %0;" : "+l"(acc) : "l"(a), "l"(b));
}
__device__ __forceinline__ unsigned long long pack2(float v) {
    unsigned long long r;
    asm("mov.b64 %0, {%1, %1};" : "=l"(r) : "f"(v));
    return r;
}
__device__ __forceinline__ void red_add_v4(float* addr, float4 v) {
    asm volatile("red.global.add.v4.f32 [%0], {%1, %2, %3, %4};"
                 :: "l"(addr), "f"(v.x), "f"(v.y), "f"(v.z), "f"(v.w) : "memory");
}

// ---------------------------------------------------------------------------
// h = leaky(x @ lin_W + lin_b)   (R6 baseline version — known-good)
// ---------------------------------------------------------------------------
__global__ void __launch_bounds__(256) k_init(const float* __restrict__ x,
                                              const float* __restrict__ W,
                                              const float* __restrict__ b) {
    __shared__ __align__(16) float sW[ND * C];
    __shared__ float sb[C];
    for (int i = threadIdx.x; i < ND * C; i += blockDim.x) sW[i] = W[i];
    if (threadIdx.x < C) sb[threadIdx.x] = b[threadIdx.x];
    __syncthreads();
    int n = blockIdx.x * blockDim.x + threadIdx.x;
    if (n >= N_NODES) return;
    float acc[C];
#pragma unroll
    for (int d = 0; d < C; d++) acc[d] = sb[d];
    const float* xr = x + (size_t)n * ND;
#pragma unroll 5
    for (int j = 0; j < ND; j++) {
        float xv = __ldg(xr + j);
#pragma unroll
        for (int d = 0; d < C; d++) acc[d] += xv * sW[j * C + d];
    }
    float4* ho = (float4*)(g_h + (size_t)n * C);
#pragma unroll
    for (int q = 0; q < 8; q++) {
        float4 v;
        float a0 = acc[4 * q], a1 = acc[4 * q + 1], a2 = acc[4 * q + 2], a3 = acc[4 * q + 3];
        v.x = a0 > 0.f ? a0 : 0.01f * a0;
        v.y = a1 > 0.f ? a1 : 0.01f * a1;
        v.z = a2 > 0.f ? a2 : 0.01f * a2;
        v.w = a3 > 0.f ? a3 : 0.01f * a3;
        ho[q] = v;
    }
}

// ---------------------------------------------------------------------------
// Precompute edge-MLP coefs for ALL layers (edge_attr is layer-invariant).
// ---------------------------------------------------------------------------
__global__ void __launch_bounds__(256) k_coef(const float* __restrict__ ea,
                                              const float* __restrict__ W1,
                                              const float* __restrict__ b1) {
    __shared__ float sW1[NL * ED * HID];
    __shared__ float sb1[NL * HID];
    if (threadIdx.x < NL * ED * HID) sW1[threadIdx.x] = W1[threadIdx.x];
    if (threadIdx.x < NL * HID) sb1[threadIdx.x] = b1[threadIdx.x];
    __syncthreads();
    int e = blockIdx.x * blockDim.x + threadIdx.x;
    if (e >= N_EDGES) return;
    float eav[ED];
    const float4* ear = (const float4*)(ea + (size_t)e * ED);
#pragma unroll
    for (int q = 0; q < 3; q++) {
        float4 v = ear[q];
        eav[4 * q] = v.x; eav[4 * q + 1] = v.y; eav[4 * q + 2] = v.z; eav[4 * q + 3] = v.w;
    }
#pragma unroll
    for (int l = 0; l < NL; l++) {
        float out[8];
#pragma unroll
        for (int k = 0; k < HID; k++) {
            float s = sb1[l * HID + k];
#pragma unroll
            for (int j = 0; j < ED; j++) s += eav[j] * sW1[(l * ED + j) * HID + k];
            out[k] = fmaxf(s, 0.f);
        }
        out[5] = 1.f; out[6] = 0.f; out[7] = 0.f;
        float4* co = (float4*)(g_coef + ((size_t)l * N_EDGES + e) * 8);
        co[0] = make_float4(out[0], out[1], out[2], out[3]);
        co[1] = make_float4(out[4], out[5], out[6], out[7]);
    }
}

// ---------------------------------------------------------------------------
// k_v: R13/R14 structure + ONE change: stores staged through smem.
// Compute phase identical (warp = slot x 32 nodes, broadcast weight LDS,
// h from sH). After compute, __syncthreads, each warp dumps its 32x32 tile
// into smem (reusing sW|sH — dead by then; stride 36 = conflict-free per
// quarter-warp), then stores cooperatively: warp-instr = 4 rows x 8 slices
// = 4 lines (vs 32 before). Store wavefronts/warp: 256 -> 32.
// All early returns converted to predication (post-compute barrier).
// ---------------------------------------------------------------------------
__global__ void __launch_bounds__(256) k_v(const float* __restrict__ W2,
                                           const float* __restrict__ b2,
                                           const float* __restrict__ rootW,
                                           const float* __restrict__ cb,
                                           const float* __restrict__ bng,
                                           const float* __restrict__ bnb,
                                           int first) {
    __shared__ __align__(16) float sm[9472];   // [0,7168)=sW, [7168,9472)=sH; reused as store buf
    __shared__ float snorm[2 * C];
    __shared__ float scb[C];
    float* sW = sm;
    float* sH = sm + 7168;

    for (int i = threadIdx.x; i < HID * C * C; i += 256) sW[i] = W2[i];
    for (int i = threadIdx.x; i < C * C; i += 256) {
        sW[5 * C * C + i] = b2[i];
        sW[6 * C * C + i] = rootW[i];
    }
    if (threadIdx.x < C) {
        scb[threadIdx.x] = cb[threadIdx.x];
        if (!first) {
            float mu = g_stats[threadIdx.x] * (1.0f / N_NODES);
            float var = g_stats[C + threadIdx.x] * (1.0f / N_NODES) - mu * mu;
            float Av = rsqrtf(var + BN_EPS) * bng[threadIdx.x];
            snorm[threadIdx.x] = Av;                             // scale
            snorm[C + threadIdx.x] = bnb[threadIdx.x] - mu * Av; // shift
        }
    }
    __syncthreads();

    int b8 = blockIdx.x * 8;
    int g0 = b8 / 7;
    int nodeBase = g0 * 32;
    const float* hin = first ? g_h : g_agg;

    // Cooperative h load: 64 rows x 8 float4 chunks, coalesced.
    for (int i = threadIdx.x; i < 64 * 8; i += 256) {
        int r = i >> 3, q = i & 7;
        int n = nodeBase + r;
        if (n < N_NODES) {
            float4 v = ((const float4*)(hin + (size_t)n * C))[q];
            if (!first) {
                int c0 = q * 4;
                v.x = v.x * snorm[c0] + snorm[C + c0];
                v.x = v.x > 0.f ? v.x : 0.01f * v.x;
                v.y = v.y * snorm[c0 + 1] + snorm[C + c0 + 1];
                v.y = v.y > 0.f ? v.y : 0.01f * v.y;
                v.z = v.z * snorm[c0 + 2] + snorm[C + c0 + 2];
                v.z = v.z > 0.f ? v.z : 0.01f * v.z;
                v.w = v.w * snorm[c0 + 3] + snorm[C + c0 + 3];
                v.w = v.w > 0.f ? v.w : 0.01f * v.w;
            }
            *(float4*)&sH[r * 36 + q * 4] = v;
        }
    }
    __syncthreads();

    int w = threadIdx.x >> 5;
    int lane = threadIdx.x & 31;
    int gw = b8 + w;
    int slot = gw % 7;
    int grp = gw / 7;
    int node = grp * 32 + lane;
    bool valid = node < N_NODES;

    unsigned long long acc[16];
#pragma unroll
    for (int j = 0; j < 16; j++) acc[j] = 0ULL;

    if (valid) {
        const float* hrow = sH + ((grp - g0) * 32 + lane) * 36;
        const float* wbase = sW + slot * C * C;
#pragma unroll
        for (int q8 = 0; q8 < 8; q8++) {
            float4 hv = *(const float4*)(hrow + q8 * 4);    // conflict-free LDS.128
            float hc[4] = {hv.x, hv.y, hv.z, hv.w};
#pragma unroll
            for (int r = 0; r < 4; r++) {
                unsigned long long p = pack2(hc[r]);
                const ulonglong2* wr = (const ulonglong2*)(wbase + (q8 * 4 + r) * C);
#pragma unroll
                for (int j = 0; j < 8; j++) {
                    ulonglong2 ww = wr[j];
                    fma2(acc[2 * j], p, ww.x);
                    fma2(acc[2 * j + 1], p, ww.y);
                }
            }
        }
    }

    // --- staged store: all warps done with sW/sH; reuse sm as per-warp tiles
    __syncthreads();
    float* myBuf = sm + w * 1152;   // 32 rows x stride 36
    if (valid) {
        const float* af = (const float*)acc;
        if (slot == 6) {
#pragma unroll
            for (int q = 0; q < 8; q++) {
                float4 v;
                v.x = af[4 * q] + scb[4 * q];
                v.y = af[4 * q + 1] + scb[4 * q + 1];
                v.z = af[4 * q + 2] + scb[4 * q + 2];
                v.w = af[4 * q + 3] + scb[4 * q + 3];
                *(float4*)&myBuf[lane * 36 + q * 4] = v;
            }
        } else {
            const float4* a4 = (const float4*)acc;
#pragma unroll
            for (int q = 0; q < 8; q++)
                *(float4*)&myBuf[lane * 36 + q * 4] = a4[q];
        }
    }
    __syncwarp();

    // cooperative warp store: instr j covers rows 4j..4j+3 x 8 slices = 4 lines
    int rowsValid = N_NODES - grp * 32;           // may be <=0 for tail warps
    if (rowsValid > 32) rowsValid = 32;
    int rsub = lane >> 3;                         // 0..3
    int q = lane & 7;                             // 0..7
    size_t rowStride = (slot == 6) ? C : 192;
    float* gbase = (slot == 6) ? (g_agg + (size_t)grp * 32 * C)
                               : (g_v + (size_t)grp * 32 * 192 + slot * C);
#pragma unroll
    for (int j = 0; j < 8; j++) {
        int r = j * 4 + rsub;
        if (r < rowsValid)
            *(float4*)(gbase + (size_t)r * rowStride + q * 4) =
                *(const float4*)&myBuf[r * 36 + q * 4];
    }
}

// ---------------------------------------------------------------------------
// Edge kernel (R6 verbatim, measured 17us): 8 lanes per edge (warp = 4 edges).
// Block 0 zeroes g_stats for this layer's k_stats.
// ---------------------------------------------------------------------------
__global__ void __launch_bounds__(256) k_edge(const int* __restrict__ src,
                                              const int* __restrict__ dst,
                                              int layer) {
    if (blockIdx.x == 0 && threadIdx.x < 2 * C) g_stats[threadIdx.x] = 0.f;

    const float* coefL = g_coef + (size_t)layer * N_EDGES * 8;

    int lane = threadIdx.x & 31;
    int warp = (blockIdx.x * blockDim.x + threadIdx.x) >> 5;
    int group = lane >> 3;
    int d4 = lane & 7;
    int e = warp * 4 + group;
    if (e >= N_EDGES) return;

    int sn = __ldg(src + e);
    int dn = __ldg(dst + e);
    const float* cp = coefL + (size_t)e * 8;
    float4 c03 = __ldg((const float4*)cp);
    float2 c45 = __ldg((const float2*)(cp + 4));
    float coef[6] = {c03.x, c03.y, c03.z, c03.w, c45.x, c45.y};

    unsigned long long a0 = 0ULL, a1 = 0ULL;
    const float* vb = g_v + (size_t)sn * (6 * C) + d4 * 4;
#pragma unroll
    for (int k = 0; k < 6; k++) {
        float ck = coef[k];
        if (ck != 0.f) {
            ulonglong2 w = __ldg((const ulonglong2*)(vb + k * C));
            unsigned long long p = pack2(ck);
            fma2(a0, p, w.x);
            fma2(a1, p, w.y);
        }
    }

    float2 lo = *(float2*)&a0, hi = *(float2*)&a1;
    red_add_v4(g_agg + (size_t)dn * C + d4 * 4, make_float4(lo.x, lo.y, hi.x, hi.y));
}

// ---------------------------------------------------------------------------
// BN statistics (R14 version — WIN): grid MUST be 296 blocks; 5 unconditional
// + 1 guarded independent LDG.128 per thread. Last layer seeds out with pred_b.
// ---------------------------------------------------------------------------
#define STAT_STRIDE (296 * 256)

__global__ void __launch_bounds__(256) k_stats(float* out, const float* __restrict__ pb,
                                               int do_out) {
    if (do_out && blockIdx.x < 2) {
        int g = blockIdx.x * 256 + threadIdx.x;
        if (g < NG) out[g] = pb[0];
    }
    __shared__ float ss[2 * C];
    if (threadIdx.x < 2 * C) ss[threadIdx.x] = 0.f;
    __syncthreads();

    const float4* A = (const float4*)g_agg;
    int base = blockIdx.x * 256 + threadIdx.x;
    float4 v0 = A[base];
    float4 v1 = A[base + STAT_STRIDE];
    float4 v2 = A[base + 2 * STAT_STRIDE];
    float4 v3 = A[base + 3 * STAT_STRIDE];
    float4 v4 = A[base + 4 * STAT_STRIDE];
    float4 s, q;
    s.x = v0.x + v1.x + v2.x + v3.x + v4.x;
    s.y = v0.y + v1.y + v2.y + v3.y + v4.y;
    s.z = v0.z + v1.z + v2.z + v3.z + v4.z;
    s.w = v0.w + v1.w + v2.w + v3.w + v4.w;
    q.x = v0.x * v0.x + v1.x * v1.x + v2.x * v2.x + v3.x * v3.x + v4.x * v4.x;
    q.y = v0.y * v0.y + v1.y * v1.y + v2.y * v2.y + v3.y * v3.y + v4.y * v4.y;
    q.z = v0.z * v0.z + v1.z * v1.z + v2.z * v2.z + v3.z * v3.z + v4.z * v4.z;
    q.w = v0.w * v0.w + v1.w * v1.w + v2.w * v2.w + v3.w * v3.w + v4.w * v4.w;
    int i5 = base + 5 * STAT_STRIDE;
    if (i5 < N_NODES * 8) {
        float4 v5 = A[i5];
        s.x += v5.x; s.y += v5.y; s.z += v5.z; s.w += v5.w;
        q.x += v5.x * v5.x; q.y += v5.y * v5.y; q.z += v5.z * v5.z; q.w += v5.w * v5.w;
    }

#pragma unroll
    for (int off = 8; off <= 16; off <<= 1) {
        s.x += __shfl_xor_sync(0xffffffffu, s.x, off);
        s.y += __shfl_xor_sync(0xffffffffu, s.y, off);
        s.z += __shfl_xor_sync(0xffffffffu, s.z, off);
        s.w += __shfl_xor_sync(0xffffffffu, s.w, off);
        q.x += __shfl_xor_sync(0xffffffffu, q.x, off);
        q.y += __shfl_xor_sync(0xffffffffu, q.y, off);
        q.z += __shfl_xor_sync(0xffffffffu, q.z, off);
        q.w += __shfl_xor_sync(0xffffffffu, q.w, off);
    }
    int lane = threadIdx.x & 31;
    if (lane < 8) {
        int cg = lane * 4;
        atomicAdd(&ss[cg + 0], s.x); atomicAdd(&ss[cg + 1], s.y);
        atomicAdd(&ss[cg + 2], s.z); atomicAdd(&ss[cg + 3], s.w);
        atomicAdd(&ss[C + cg + 0], q.x); atomicAdd(&ss[C + cg + 1], q.y);
        atomicAdd(&ss[C + cg + 2], q.z); atomicAdd(&ss[C + cg + 3], q.w);
    }
    __syncthreads();
    if (threadIdx.x < 2 * C) atomicAdd(&g_stats[threadIdx.x], ss[threadIdx.x]);
}

// ---------------------------------------------------------------------------
// Final: BN (no leaky) + prediction dot + scatter to graphs (batch is sorted).
// ---------------------------------------------------------------------------
__global__ void __launch_bounds__(256) k_fin(const int* __restrict__ batch,
                                             const float* __restrict__ pW,
                                             const float* __restrict__ bng,
                                             const float* __restrict__ bnb,
                                             float* out) {
    __shared__ float snorm[4 * C];
    __shared__ float spw[C];
    if (threadIdx.x < C) {
        float mu = g_stats[threadIdx.x] * (1.0f / N_NODES);
        float var = g_stats[C + threadIdx.x] * (1.0f / N_NODES) - mu * mu;
        snorm[threadIdx.x] = mu;
        snorm[C + threadIdx.x] = rsqrtf(var + BN_EPS);
        snorm[2 * C + threadIdx.x] = bng[threadIdx.x];
        snorm[3 * C + threadIdx.x] = bnb[threadIdx.x];
        spw[threadIdx.x] = pW[threadIdx.x];
    }
    __syncthreads();
    int n = blockIdx.x * blockDim.x + threadIdx.x;
    bool valid = n < N_NODES;
    int nn = valid ? n : N_NODES - 1;
    const float4* ap = (const float4*)(g_agg + (size_t)nn * C);
    float s = 0.f;
#pragma unroll
    for (int q = 0; q < 8; q++) {
        float4 v = ap[q];
        float t[4] = {v.x, v.y, v.z, v.w};
#pragma unroll
        for (int r = 0; r < 4; r++) {
            int c = 4 * q + r;
            float val = (t[r] - snorm[c]) * snorm[C + c] * snorm[2 * C + c] + snorm[3 * C + c];
            s += val * spw[c];
        }
    }
    if (!valid) s = 0.f;
    int bid = batch[nn];
    int bid0 = __shfl_sync(0xffffffffu, bid, 0);
    bool uni = __all_sync(0xffffffffu, bid == bid0 && valid);
    if (uni) {
#pragma unroll
        for (int off = 16; off >= 1; off >>= 1)
            s += __shfl_xor_sync(0xffffffffu, s, off);
        if ((threadIdx.x & 31) == 0) atomicAdd(&out[bid0], s);
    } else if (valid) {
        atomicAdd(&out[bid], s);
    }
}

// ---------------------------------------------------------------------------
extern "C" void kernel_launch(void* const* d_in, const int* in_sizes, int n_in,
                              void* d_out, int out_size) {
    const float* x       = (const float*)d_in[0];
    const int*   ei      = (const int*)d_in[1];
    const float* ea      = (const float*)d_in[2];
    const int*   batch   = (const int*)d_in[3];
    const float* lin_W   = (const float*)d_in[4];
    const float* lin_b   = (const float*)d_in[5];
    const float* mes_W1  = (const float*)d_in[6];
    const float* mes_b1  = (const float*)d_in[7];
    const float* mes_W2  = (const float*)d_in[8];
    const float* mes_b2  = (const float*)d_in[9];
    const float* root_W  = (const float*)d_in[10];
    const float* conv_b  = (const float*)d_in[11];
    const float* bn_g    = (const float*)d_in[12];
    const float* bn_b    = (const float*)d_in[13];
    const float* pred_W  = (const float*)d_in[14];
    const float* pred_b  = (const float*)d_in[15];
    float* out = (float*)d_out;

    const int* src = ei;
    const int* dst = ei + N_EDGES;

    int vwarps = 7 * ((N_NODES + 31) / 32);
    int vblocks = (vwarps + 7) / 8;                  // 1368
    int eblocks = (N_EDGES / 4 * 32 + 255) / 256;    // 6250

    k_init<<<(N_NODES + 255) / 256, 256>>>(x, lin_W, lin_b);
    k_coef<<<(N_EDGES + 255) / 256, 256>>>(ea, mes_W1, mes_b1);
    for (int l = 0; l < NL; l++) {
        k_v<<<vblocks, 256>>>(mes_W2 + l * HID * C * C, mes_b2 + l * C * C,
                              root_W + l * C * C, conv_b + l * C,
                              l > 0 ? bn_g + (l - 1) * C : bn_g,
                              l > 0 ? bn_b + (l - 1) * C : bn_b,
                              l == 0 ? 1 : 0);
        k_edge<<<eblocks, 256>>>(src, dst, l);
        k_stats<<<296, 256>>>(out, pred_b, l == NL - 1 ? 1 : 0);
    }
    k_fin<<<(N_NODES + 255) / 256, 256>>>(batch, pred_W, bn_g + 2 * C, bn_b + 2 * C, out);
}

// round 16
// speedup vs baseline: 1.4995x; 1.0075x over previous
#include <cuda_runtime.h>

#define N_NODES 50000
#define N_EDGES 200000
#define C 32
#define ND 75
#define ED 12
#define NL 3
#define NG 500
#define HID 5
#define BN_EPS 1e-5f

#define INIT_BLOCKS 196        // (N_NODES+255)/256
#define COEF_BLOCKS 782        // (N_EDGES+255)/256

// Scratch (no allocations allowed)
__device__ __align__(128) float g_h[N_NODES * C];         // layer-0 features
__device__ __align__(128) float g_agg[N_NODES * C];       // conv accumulator
__device__ __align__(128) float g_v[N_NODES * 6 * C];     // v[n,k,d]
__device__ __align__(128) float g_coef[NL * N_EDGES * 8]; // edge MLP coefs, padded
__device__ float g_stats[2 * C];                          // BN sum / sumsq

// ---- packed fp32x2 helpers (sm_103a) ----
__device__ __forceinline__ void fma2(unsigned long long& acc, unsigned long long a,
                                     unsigned long long b) {
    asm("fma.rn.f32x2 %0, %1, %2, %0;" : "+l"(acc) : "l"(a), "l"(b));
}
__device__ __forceinline__ unsigned long long pack2(float v) {
    unsigned long long r;
    asm("mov.b64 %0, {%1, %1};" : "=l"(r) : "f"(v));
    return r;
}
__device__ __forceinline__ void red_add_v4(float* addr, float4 v) {
    asm volatile("red.global.add.v4.f32 [%0], {%1, %2, %3, %4};"
                 :: "l"(addr), "f"(v.x), "f"(v.y), "f"(v.z), "f"(v.w) : "memory");
}

// ---------------------------------------------------------------------------
// Fused prologue (single change this round): blocks [0,INIT_BLOCKS) run the
// R6 k_init body verbatim; blocks [INIT_BLOCKS, INIT_BLOCKS+COEF_BLOCKS) run
// the k_coef body verbatim. The two are independent (x->g_h, ea->g_coef).
// ---------------------------------------------------------------------------
__global__ void __launch_bounds__(256) k_pro(const float* __restrict__ x,
                                             const float* __restrict__ W,
                                             const float* __restrict__ b,
                                             const float* __restrict__ ea,
                                             const float* __restrict__ W1,
                                             const float* __restrict__ b1) {
    __shared__ __align__(16) float sW[ND * C];
    __shared__ float sb[C];
    __shared__ float sW1[NL * ED * HID];
    __shared__ float sb1[NL * HID];

    if (blockIdx.x < INIT_BLOCKS) {
        // ---- k_init body (R6 verbatim) ----
        for (int i = threadIdx.x; i < ND * C; i += blockDim.x) sW[i] = W[i];
        if (threadIdx.x < C) sb[threadIdx.x] = b[threadIdx.x];
        __syncthreads();
        int n = blockIdx.x * blockDim.x + threadIdx.x;
        if (n >= N_NODES) return;
        float acc[C];
#pragma unroll
        for (int d = 0; d < C; d++) acc[d] = sb[d];
        const float* xr = x + (size_t)n * ND;
#pragma unroll 5
        for (int j = 0; j < ND; j++) {
            float xv = __ldg(xr + j);
#pragma unroll
            for (int d = 0; d < C; d++) acc[d] += xv * sW[j * C + d];
        }
        float4* ho = (float4*)(g_h + (size_t)n * C);
#pragma unroll
        for (int q = 0; q < 8; q++) {
            float4 v;
            float a0 = acc[4 * q], a1 = acc[4 * q + 1];
            float a2 = acc[4 * q + 2], a3 = acc[4 * q + 3];
            v.x = a0 > 0.f ? a0 : 0.01f * a0;
            v.y = a1 > 0.f ? a1 : 0.01f * a1;
            v.z = a2 > 0.f ? a2 : 0.01f * a2;
            v.w = a3 > 0.f ? a3 : 0.01f * a3;
            ho[q] = v;
        }
    } else {
        // ---- k_coef body (verbatim) ----
        if (threadIdx.x < NL * ED * HID) sW1[threadIdx.x] = W1[threadIdx.x];
        if (threadIdx.x < NL * HID) sb1[threadIdx.x] = b1[threadIdx.x];
        __syncthreads();
        int e = (blockIdx.x - INIT_BLOCKS) * blockDim.x + threadIdx.x;
        if (e >= N_EDGES) return;
        float eav[ED];
        const float4* ear = (const float4*)(ea + (size_t)e * ED);
#pragma unroll
        for (int q = 0; q < 3; q++) {
            float4 v = ear[q];
            eav[4 * q] = v.x; eav[4 * q + 1] = v.y;
            eav[4 * q + 2] = v.z; eav[4 * q + 3] = v.w;
        }
#pragma unroll
        for (int l = 0; l < NL; l++) {
            float out[8];
#pragma unroll
            for (int k = 0; k < HID; k++) {
                float s = sb1[l * HID + k];
#pragma unroll
                for (int j = 0; j < ED; j++) s += eav[j] * sW1[(l * ED + j) * HID + k];
                out[k] = fmaxf(s, 0.f);
            }
            out[5] = 1.f; out[6] = 0.f; out[7] = 0.f;
            float4* co = (float4*)(g_coef + ((size_t)l * N_EDGES + e) * 8);
            co[0] = make_float4(out[0], out[1], out[2], out[3]);
            co[1] = make_float4(out[4], out[5], out[6], out[7]);
        }
    }
}

// ---------------------------------------------------------------------------
// k_v (R15 version — WIN): h staged through smem, stores staged through smem.
// ---------------------------------------------------------------------------
__global__ void __launch_bounds__(256) k_v(const float* __restrict__ W2,
                                           const float* __restrict__ b2,
                                           const float* __restrict__ rootW,
                                           const float* __restrict__ cb,
                                           const float* __restrict__ bng,
                                           const float* __restrict__ bnb,
                                           int first) {
    __shared__ __align__(16) float sm[9472];   // [0,7168)=sW, [7168,9472)=sH; reused as store buf
    __shared__ float snorm[2 * C];
    __shared__ float scb[C];
    float* sW = sm;
    float* sH = sm + 7168;

    for (int i = threadIdx.x; i < HID * C * C; i += 256) sW[i] = W2[i];
    for (int i = threadIdx.x; i < C * C; i += 256) {
        sW[5 * C * C + i] = b2[i];
        sW[6 * C * C + i] = rootW[i];
    }
    if (threadIdx.x < C) {
        scb[threadIdx.x] = cb[threadIdx.x];
        if (!first) {
            float mu = g_stats[threadIdx.x] * (1.0f / N_NODES);
            float var = g_stats[C + threadIdx.x] * (1.0f / N_NODES) - mu * mu;
            float Av = rsqrtf(var + BN_EPS) * bng[threadIdx.x];
            snorm[threadIdx.x] = Av;                             // scale
            snorm[C + threadIdx.x] = bnb[threadIdx.x] - mu * Av; // shift
        }
    }
    __syncthreads();

    int b8 = blockIdx.x * 8;
    int g0 = b8 / 7;
    int nodeBase = g0 * 32;
    const float* hin = first ? g_h : g_agg;

    // Cooperative h load: 64 rows x 8 float4 chunks, coalesced.
    for (int i = threadIdx.x; i < 64 * 8; i += 256) {
        int r = i >> 3, q = i & 7;
        int n = nodeBase + r;
        if (n < N_NODES) {
            float4 v = ((const float4*)(hin + (size_t)n * C))[q];
            if (!first) {
                int c0 = q * 4;
                v.x = v.x * snorm[c0] + snorm[C + c0];
                v.x = v.x > 0.f ? v.x : 0.01f * v.x;
                v.y = v.y * snorm[c0 + 1] + snorm[C + c0 + 1];
                v.y = v.y > 0.f ? v.y : 0.01f * v.y;
                v.z = v.z * snorm[c0 + 2] + snorm[C + c0 + 2];
                v.z = v.z > 0.f ? v.z : 0.01f * v.z;
                v.w = v.w * snorm[c0 + 3] + snorm[C + c0 + 3];
                v.w = v.w > 0.f ? v.w : 0.01f * v.w;
            }
            *(float4*)&sH[r * 36 + q * 4] = v;
        }
    }
    __syncthreads();

    int w = threadIdx.x >> 5;
    int lane = threadIdx.x & 31;
    int gw = b8 + w;
    int slot = gw % 7;
    int grp = gw / 7;
    int node = grp * 32 + lane;
    bool valid = node < N_NODES;

    unsigned long long acc[16];
#pragma unroll
    for (int j = 0; j < 16; j++) acc[j] = 0ULL;

    if (valid) {
        const float* hrow = sH + ((grp - g0) * 32 + lane) * 36;
        const float* wbase = sW + slot * C * C;
#pragma unroll
        for (int q8 = 0; q8 < 8; q8++) {
            float4 hv = *(const float4*)(hrow + q8 * 4);    // conflict-free LDS.128
            float hc[4] = {hv.x, hv.y, hv.z, hv.w};
#pragma unroll
            for (int r = 0; r < 4; r++) {
                unsigned long long p = pack2(hc[r]);
                const ulonglong2* wr = (const ulonglong2*)(wbase + (q8 * 4 + r) * C);
#pragma unroll
                for (int j = 0; j < 8; j++) {
                    ulonglong2 ww = wr[j];
                    fma2(acc[2 * j], p, ww.x);
                    fma2(acc[2 * j + 1], p, ww.y);
                }
            }
        }
    }

    // --- staged store: all warps done with sW/sH; reuse sm as per-warp tiles
    __syncthreads();
    float* myBuf = sm + w * 1152;   // 32 rows x stride 36
    if (valid) {
        const float* af = (const float*)acc;
        if (slot == 6) {
#pragma unroll
            for (int q = 0; q < 8; q++) {
                float4 v;
                v.x = af[4 * q] + scb[4 * q];
                v.y = af[4 * q + 1] + scb[4 * q + 1];
                v.z = af[4 * q + 2] + scb[4 * q + 2];
                v.w = af[4 * q + 3] + scb[4 * q + 3];
                *(float4*)&myBuf[lane * 36 + q * 4] = v;
            }
        } else {
            const float4* a4 = (const float4*)acc;
#pragma unroll
            for (int q = 0; q < 8; q++)
                *(float4*)&myBuf[lane * 36 + q * 4] = a4[q];
        }
    }
    __syncwarp();

    // cooperative warp store: instr j covers rows 4j..4j+3 x 8 slices = 4 lines
    int rowsValid = N_NODES - grp * 32;
    if (rowsValid > 32) rowsValid = 32;
    int rsub = lane >> 3;
    int q = lane & 7;
    size_t rowStride = (slot == 6) ? C : 192;
    float* gbase = (slot == 6) ? (g_agg + (size_t)grp * 32 * C)
                               : (g_v + (size_t)grp * 32 * 192 + slot * C);
#pragma unroll
    for (int j = 0; j < 8; j++) {
        int r = j * 4 + rsub;
        if (r < rowsValid)
            *(float4*)(gbase + (size_t)r * rowStride + q * 4) =
                *(const float4*)&myBuf[r * 36 + q * 4];
    }
}

// ---------------------------------------------------------------------------
// Edge kernel (R6 verbatim, measured ~17us): 8 lanes per edge (warp = 4 edges).
// Block 0 zeroes g_stats for this layer's k_stats.
// ---------------------------------------------------------------------------
__global__ void __launch_bounds__(256) k_edge(const int* __restrict__ src,
                                              const int* __restrict__ dst,
                                              int layer) {
    if (blockIdx.x == 0 && threadIdx.x < 2 * C) g_stats[threadIdx.x] = 0.f;

    const float* coefL = g_coef + (size_t)layer * N_EDGES * 8;

    int lane = threadIdx.x & 31;
    int warp = (blockIdx.x * blockDim.x + threadIdx.x) >> 5;
    int group = lane >> 3;
    int d4 = lane & 7;
    int e = warp * 4 + group;
    if (e >= N_EDGES) return;

    int sn = __ldg(src + e);
    int dn = __ldg(dst + e);
    const float* cp = coefL + (size_t)e * 8;
    float4 c03 = __ldg((const float4*)cp);
    float2 c45 = __ldg((const float2*)(cp + 4));
    float coef[6] = {c03.x, c03.y, c03.z, c03.w, c45.x, c45.y};

    unsigned long long a0 = 0ULL, a1 = 0ULL;
    const float* vb = g_v + (size_t)sn * (6 * C) + d4 * 4;
#pragma unroll
    for (int k = 0; k < 6; k++) {
        float ck = coef[k];
        if (ck != 0.f) {
            ulonglong2 w = __ldg((const ulonglong2*)(vb + k * C));
            unsigned long long p = pack2(ck);
            fma2(a0, p, w.x);
            fma2(a1, p, w.y);
        }
    }

    float2 lo = *(float2*)&a0, hi = *(float2*)&a1;
    red_add_v4(g_agg + (size_t)dn * C + d4 * 4, make_float4(lo.x, lo.y, hi.x, hi.y));
}

// ---------------------------------------------------------------------------
// BN statistics (R14 version — WIN): grid MUST be 296 blocks; 5 unconditional
// + 1 guarded independent LDG.128 per thread. Last layer seeds out with pred_b.
// ---------------------------------------------------------------------------
#define STAT_STRIDE (296 * 256)

__global__ void __launch_bounds__(256) k_stats(float* out, const float* __restrict__ pb,
                                               int do_out) {
    if (do_out && blockIdx.x < 2) {
        int g = blockIdx.x * 256 + threadIdx.x;
        if (g < NG) out[g] = pb[0];
    }
    __shared__ float ss[2 * C];
    if (threadIdx.x < 2 * C) ss[threadIdx.x] = 0.f;
    __syncthreads();

    const float4* A = (const float4*)g_agg;
    int base = blockIdx.x * 256 + threadIdx.x;
    float4 v0 = A[base];
    float4 v1 = A[base + STAT_STRIDE];
    float4 v2 = A[base + 2 * STAT_STRIDE];
    float4 v3 = A[base + 3 * STAT_STRIDE];
    float4 v4 = A[base + 4 * STAT_STRIDE];
    float4 s, q;
    s.x = v0.x + v1.x + v2.x + v3.x + v4.x;
    s.y = v0.y + v1.y + v2.y + v3.y + v4.y;
    s.z = v0.z + v1.z + v2.z + v3.z + v4.z;
    s.w = v0.w + v1.w + v2.w + v3.w + v4.w;
    q.x = v0.x * v0.x + v1.x * v1.x + v2.x * v2.x + v3.x * v3.x + v4.x * v4.x;
    q.y = v0.y * v0.y + v1.y * v1.y + v2.y * v2.y + v3.y * v3.y + v4.y * v4.y;
    q.z = v0.z * v0.z + v1.z * v1.z + v2.z * v2.z + v3.z * v3.z + v4.z * v4.z;
    q.w = v0.w * v0.w + v1.w * v1.w + v2.w * v2.w + v3.w * v3.w + v4.w * v4.w;
    int i5 = base + 5 * STAT_STRIDE;
    if (i5 < N_NODES * 8) {
        float4 v5 = A[i5];
        s.x += v5.x; s.y += v5.y; s.z += v5.z; s.w += v5.w;
        q.x += v5.x * v5.x; q.y += v5.y * v5.y; q.z += v5.z * v5.z; q.w += v5.w * v5.w;
    }

#pragma unroll
    for (int off = 8; off <= 16; off <<= 1) {
        s.x += __shfl_xor_sync(0xffffffffu, s.x, off);
        s.y += __shfl_xor_sync(0xffffffffu, s.y, off);
        s.z += __shfl_xor_sync(0xffffffffu, s.z, off);
        s.w += __shfl_xor_sync(0xffffffffu, s.w, off);
        q.x += __shfl_xor_sync(0xffffffffu, q.x, off);
        q.y += __shfl_xor_sync(0xffffffffu, q.y, off);
        q.z += __shfl_xor_sync(0xffffffffu, q.z, off);
        q.w += __shfl_xor_sync(0xffffffffu, q.w, off);
    }
    int lane = threadIdx.x & 31;
    if (lane < 8) {
        int cg = lane * 4;
        atomicAdd(&ss[cg + 0], s.x); atomicAdd(&ss[cg + 1], s.y);
        atomicAdd(&ss[cg + 2], s.z); atomicAdd(&ss[cg + 3], s.w);
        atomicAdd(&ss[C + cg + 0], q.x); atomicAdd(&ss[C + cg + 1], q.y);
        atomicAdd(&ss[C + cg + 2], q.z); atomicAdd(&ss[C + cg + 3], q.w);
    }
    __syncthreads();
    if (threadIdx.x < 2 * C) atomicAdd(&g_stats[threadIdx.x], ss[threadIdx.x]);
}

// ---------------------------------------------------------------------------
// Final: BN (no leaky) + prediction dot + scatter to graphs (batch is sorted).
// ---------------------------------------------------------------------------
__global__ void __launch_bounds__(256) k_fin(const int* __restrict__ batch,
                                             const float* __restrict__ pW,
                                             const float* __restrict__ bng,
                                             const float* __restrict__ bnb,
                                             float* out) {
    __shared__ float snorm[4 * C];
    __shared__ float spw[C];
    if (threadIdx.x < C) {
        float mu = g_stats[threadIdx.x] * (1.0f / N_NODES);
        float var = g_stats[C + threadIdx.x] * (1.0f / N_NODES) - mu * mu;
        snorm[threadIdx.x] = mu;
        snorm[C + threadIdx.x] = rsqrtf(var + BN_EPS);
        snorm[2 * C + threadIdx.x] = bng[threadIdx.x];
        snorm[3 * C + threadIdx.x] = bnb[threadIdx.x];
        spw[threadIdx.x] = pW[threadIdx.x];
    }
    __syncthreads();
    int n = blockIdx.x * blockDim.x + threadIdx.x;
    bool valid = n < N_NODES;
    int nn = valid ? n : N_NODES - 1;
    const float4* ap = (const float4*)(g_agg + (size_t)nn * C);
    float s = 0.f;
#pragma unroll
    for (int q = 0; q < 8; q++) {
        float4 v = ap[q];
        float t[4] = {v.x, v.y, v.z, v.w};
#pragma unroll
        for (int r = 0; r < 4; r++) {
            int c = 4 * q + r;
            float val = (t[r] - snorm[c]) * snorm[C + c] * snorm[2 * C + c] + snorm[3 * C + c];
            s += val * spw[c];
        }
    }
    if (!valid) s = 0.f;
    int bid = batch[nn];
    int bid0 = __shfl_sync(0xffffffffu, bid, 0);
    bool uni = __all_sync(0xffffffffu, bid == bid0 && valid);
    if (uni) {
#pragma unroll
        for (int off = 16; off >= 1; off >>= 1)
            s += __shfl_xor_sync(0xffffffffu, s, off);
        if ((threadIdx.x & 31) == 0) atomicAdd(&out[bid0], s);
    } else if (valid) {
        atomicAdd(&out[bid], s);
    }
}

// ---------------------------------------------------------------------------
extern "C" void kernel_launch(void* const* d_in, const int* in_sizes, int n_in,
                              void* d_out, int out_size) {
    const float* x       = (const float*)d_in[0];
    const int*   ei      = (const int*)d_in[1];
    const float* ea      = (const float*)d_in[2];
    const int*   batch   = (const int*)d_in[3];
    const float* lin_W   = (const float*)d_in[4];
    const float* lin_b   = (const float*)d_in[5];
    const float* mes_W1  = (const float*)d_in[6];
    const float* mes_b1  = (const float*)d_in[7];
    const float* mes_W2  = (const float*)d_in[8];
    const float* mes_b2  = (const float*)d_in[9];
    const float* root_W  = (const float*)d_in[10];
    const float* conv_b  = (const float*)d_in[11];
    const float* bn_g    = (const float*)d_in[12];
    const float* bn_b    = (const float*)d_in[13];
    const float* pred_W  = (const float*)d_in[14];
    const float* pred_b  = (const float*)d_in[15];
    float* out = (float*)d_out;

    const int* src = ei;
    const int* dst = ei + N_EDGES;

    int vwarps = 7 * ((N_NODES + 31) / 32);
    int vblocks = (vwarps + 7) / 8;                  // 1368
    int eblocks = (N_EDGES / 4 * 32 + 255) / 256;    // 6250

    k_pro<<<INIT_BLOCKS + COEF_BLOCKS, 256>>>(x, lin_W, lin_b, ea, mes_W1, mes_b1);
    for (int l = 0; l < NL; l++) {
        k_v<<<vblocks, 256>>>(mes_W2 + l * HID * C * C, mes_b2 + l * C * C,
                              root_W + l * C * C, conv_b + l * C,
                              l > 0 ? bn_g + (l - 1) * C : bn_g,
                              l > 0 ? bn_b + (l - 1) * C : bn_b,
                              l == 0 ? 1 : 0);
        k_edge<<<eblocks, 256>>>(src, dst, l);
        k_stats<<<296, 256>>>(out, pred_b, l == NL - 1 ? 1 : 0);
    }
    k_fin<<<(N_NODES + 255) / 256, 256>>>(batch, pred_W, bn_g + 2 * C, bn_b + 2 * C, out);
}